// round 1
// baseline (speedup 1.0000x reference)
#include <cuda_runtime.h>
#include <math.h>

#define T_      2048
#define HID_    2560
#define H_      40
#define NOPE_   64
#define ROPE_   32
#define VDIM_   64
#define QLORA_  768
#define KVLORA_ 256
#define DQK     288   // KVLORA + ROPE
#define QHD     96    // NOPE + ROPE
#define EPS_    1e-5f

// ---------------- scratch (device globals, allocation-free) ----------------
__device__ float sc_qa  [T_ * QLORA_];
__device__ float sc_qan [T_ * QLORA_];
__device__ float sc_q   [T_ * H_ * QHD];
__device__ float sc_lat [T_ * DQK];
__device__ float sc_kin [T_ * DQK];                 // [T,288]: v_in(256) | roped k_pe(32)
__device__ float sc_qin [(size_t)T_ * H_ * DQK];    // [T,H,288]: q_lat(256) | roped q_pe(32)
__device__ float sc_olat[(size_t)T_ * H_ * KVLORA_];// [T,H,256]
__device__ float sc_ov  [T_ * H_ * VDIM_];          // [T,2560]

// ---------------- generic batched SGEMM: C = A @ B ----------------
// 128x128 tile, BK=8, 256 threads, 8x8 per thread.
__global__ void sgemm128(const float* __restrict__ A, const float* __restrict__ B,
                         float* __restrict__ C,
                         int M, int N, int K, int lda, int ldb, int ldc,
                         long sA, long sB, long sC)
{
    __shared__ float As[8][128];
    __shared__ float Bs[8][132];

    const float* Ab = A + (long)blockIdx.z * sA;
    const float* Bb = B + (long)blockIdx.z * sB;
    float*       Cb = C + (long)blockIdx.z * sC;

    int bm0 = blockIdx.y * 128;
    int bn0 = blockIdx.x * 128;
    int tid = threadIdx.x;
    int tx  = tid & 15;
    int ty  = tid >> 4;

    float acc[8][8];
#pragma unroll
    for (int i = 0; i < 8; i++)
#pragma unroll
        for (int j = 0; j < 8; j++) acc[i][j] = 0.f;

    for (int k0 = 0; k0 < K; k0 += 8) {
#pragma unroll
        for (int i = 0; i < 4; i++) {               // A tile: 128 rows x 8 cols (transposed)
            int idx = tid + i * 256;
            int r = idx >> 3, c = idx & 7;
            int gr = bm0 + r;
            As[c][r] = (gr < M) ? Ab[(long)gr * lda + (k0 + c)] : 0.f;
        }
#pragma unroll
        for (int i = 0; i < 4; i++) {               // B tile: 8 rows x 128 cols
            int idx = tid + i * 256;
            int kr = idx >> 7, nc = idx & 127;
            int gn = bn0 + nc;
            Bs[kr][nc] = (gn < N) ? Bb[(long)(k0 + kr) * ldb + gn] : 0.f;
        }
        __syncthreads();
#pragma unroll
        for (int kk = 0; kk < 8; kk++) {
            float4 a0 = *(const float4*)&As[kk][ty * 8];
            float4 a1 = *(const float4*)&As[kk][ty * 8 + 4];
            float4 b0 = *(const float4*)&Bs[kk][tx * 8];
            float4 b1 = *(const float4*)&Bs[kk][tx * 8 + 4];
            float av[8] = {a0.x, a0.y, a0.z, a0.w, a1.x, a1.y, a1.z, a1.w};
            float bv[8] = {b0.x, b0.y, b0.z, b0.w, b1.x, b1.y, b1.z, b1.w};
#pragma unroll
            for (int i = 0; i < 8; i++)
#pragma unroll
                for (int j = 0; j < 8; j++) acc[i][j] += av[i] * bv[j];
        }
        __syncthreads();
    }

#pragma unroll
    for (int i = 0; i < 8; i++) {
        int gr = bm0 + ty * 8 + i;
        if (gr >= M) continue;
#pragma unroll
        for (int j = 0; j < 8; j++) {
            int gn = bn0 + tx * 8 + j;
            if (gn < N) Cb[(long)gr * ldc + gn] = acc[i][j];
        }
    }
}

// ---------------- RMSNorm over 768 (q LoRA) ----------------
__global__ void rms768_kernel(const float* __restrict__ in, const float* __restrict__ g,
                              float* __restrict__ out)
{
    int t = blockIdx.x;
    const float* x = in + (long)t * QLORA_;
    int tid = threadIdx.x; // 256
    __shared__ float red[256];
    float s = 0.f;
    for (int i = tid; i < QLORA_; i += 256) { float v = x[i]; s += v * v; }
    red[tid] = s;
    __syncthreads();
    for (int st = 128; st > 0; st >>= 1) { if (tid < st) red[tid] += red[tid + st]; __syncthreads(); }
    __shared__ float rinv;
    if (tid == 0) rinv = rsqrtf(red[0] / (float)QLORA_ + EPS_);
    __syncthreads();
    for (int i = tid; i < QLORA_; i += 256)
        out[(long)t * QLORA_ + i] = x[i] * rinv * g[i];
}

// ---------------- latent -> k_in: RMSNorm(256) + RoPE(k_pe) ----------------
__global__ void latent_kernel(const float* __restrict__ lat, const float* __restrict__ g,
                              const int* __restrict__ pos, float* __restrict__ kin)
{
    int t = blockIdx.x;
    const float* x = lat + (long)t * DQK;
    int tid = threadIdx.x; // 256
    __shared__ float red[256];
    float v = x[tid];
    red[tid] = v * v;
    __syncthreads();
    for (int st = 128; st > 0; st >>= 1) { if (tid < st) red[tid] += red[tid + st]; __syncthreads(); }
    __shared__ float rinv;
    if (tid == 0) rinv = rsqrtf(red[0] / (float)KVLORA_ + EPS_);
    __syncthreads();
    kin[(long)t * DQK + tid] = v * rinv * g[tid];
    if (tid < 16) {
        float p = (float)pos[t];
        float f = p * powf(10000.f, -(float)tid / 16.f);
        float c = cosf(f), s = sinf(f);
        float x1 = x[KVLORA_ + tid];
        float x2 = x[KVLORA_ + 16 + tid];
        kin[(long)t * DQK + KVLORA_ + tid]      = x1 * c - x2 * s;
        kin[(long)t * DQK + KVLORA_ + 16 + tid] = x2 * c + x1 * s;
    }
}

// ---------------- RoPE on q_pe -> q_in[...,256:288] ----------------
__global__ void rope_q_kernel(const float* __restrict__ q, const int* __restrict__ pos,
                              float* __restrict__ qin)
{
    int idx = blockIdx.x * blockDim.x + threadIdx.x;
    if (idx >= T_ * H_ * 16) return;
    int j = idx & 15;
    int h = (idx >> 4) % H_;
    int t = idx / (16 * H_);
    float p = (float)pos[t];
    float f = p * powf(10000.f, -(float)j / 16.f);
    float c = cosf(f), s = sinf(f);
    const float* qp = q + (long)t * (H_ * QHD) + h * QHD + NOPE_;
    float x1 = qp[j], x2 = qp[16 + j];
    float* o = qin + (long)t * (H_ * DQK) + h * DQK + KVLORA_;
    o[j]      = x1 * c - x2 * s;
    o[16 + j] = x2 * c + x1 * s;
}

// ---------------- flash attention: BM=64 queries, BN=32 keys ----------------
#define QPAD 292
#define VPAD 260
#define SPAD 33
#define ATTN_SMEM ((64*QPAD + 32*QPAD + 32*VPAD + 64*SPAD + 3*64) * 4)

__global__ void attn_kernel(const float* __restrict__ qin, const float* __restrict__ kin,
                            float* __restrict__ olat)
{
    extern __shared__ float sm[];
    float* Qs  = sm;                    // [64][292]
    float* Ks  = Qs + 64 * QPAD;        // [32][292]
    float* Vs  = Ks + 32 * QPAD;        // [32][260]
    float* Ss  = Vs + 32 * VPAD;        // [64][33]
    float* m_s = Ss + 64 * SPAD;        // [64]
    float* l_s = m_s + 64;
    float* a_s = l_s + 64;

    const int h  = blockIdx.y;
    const int qb = blockIdx.x;
    const int i0 = qb * 64;
    const int tid = threadIdx.x;        // 256

    for (int idx = tid; idx < 64 * DQK; idx += 256) {
        int r = idx / DQK, c = idx % DQK;
        Qs[r * QPAD + c] = qin[(long)(i0 + r) * (H_ * DQK) + h * DQK + c];
    }
    if (tid < 64) { m_s[tid] = -1e30f; l_s[tid] = 0.f; }

    float acc0[32], acc1[32];
#pragma unroll
    for (int j = 0; j < 32; j++) { acc0[j] = 0.f; acc1[j] = 0.f; }

    const int r0  = (tid >> 3) * 2;       // O rows (2)
    const int c0  = (tid & 7) * 32;       // O cols (32)
    const int srg = (tid >> 4) * 4;       // S rows (4)
    const int scg = (tid & 15) * 2;       // S cols (2)
    const float scale = 0.1020620726f;    // 1/sqrt(96)

    const int nkb = 2 * qb + 2;
    for (int kb = 0; kb < nkb; kb++) {
        __syncthreads();
        const int j0 = kb * 32;
        for (int idx = tid; idx < 32 * DQK; idx += 256) {
            int r = idx / DQK, c = idx % DQK;
            Ks[r * QPAD + c] = kin[(long)(j0 + r) * DQK + c];
        }
        for (int idx = tid; idx < 32 * 256; idx += 256) {
            int r = idx >> 8, c = idx & 255;
            Vs[r * VPAD + c] = kin[(long)(j0 + r) * DQK + c];
        }
        __syncthreads();

        // S = Q K^T  (4 rows x 2 cols per thread)
        float s00 = 0.f, s01 = 0.f, s10 = 0.f, s11 = 0.f, s20 = 0.f, s21 = 0.f, s30 = 0.f, s31 = 0.f;
        for (int k = 0; k < DQK; k += 4) {
            float4 k0v = *(const float4*)&Ks[scg * QPAD + k];
            float4 k1v = *(const float4*)&Ks[(scg + 1) * QPAD + k];
            float4 q0 = *(const float4*)&Qs[(srg + 0) * QPAD + k];
            float4 q1 = *(const float4*)&Qs[(srg + 1) * QPAD + k];
            float4 q2 = *(const float4*)&Qs[(srg + 2) * QPAD + k];
            float4 q3 = *(const float4*)&Qs[(srg + 3) * QPAD + k];
            s00 += q0.x*k0v.x + q0.y*k0v.y + q0.z*k0v.z + q0.w*k0v.w;
            s01 += q0.x*k1v.x + q0.y*k1v.y + q0.z*k1v.z + q0.w*k1v.w;
            s10 += q1.x*k0v.x + q1.y*k0v.y + q1.z*k0v.z + q1.w*k0v.w;
            s11 += q1.x*k1v.x + q1.y*k1v.y + q1.z*k1v.z + q1.w*k1v.w;
            s20 += q2.x*k0v.x + q2.y*k0v.y + q2.z*k0v.z + q2.w*k0v.w;
            s21 += q2.x*k1v.x + q2.y*k1v.y + q2.z*k1v.z + q2.w*k1v.w;
            s30 += q3.x*k0v.x + q3.y*k0v.y + q3.z*k0v.z + q3.w*k0v.w;
            s31 += q3.x*k1v.x + q3.y*k1v.y + q3.z*k1v.z + q3.w*k1v.w;
        }
        {
            float sv[4][2] = {{s00,s01},{s10,s11},{s20,s21},{s30,s31}};
#pragma unroll
            for (int rr = 0; rr < 4; rr++)
#pragma unroll
                for (int cc = 0; cc < 2; cc++) {
                    int gi = i0 + srg + rr, gj = j0 + scg + cc;
                    float val = sv[rr][cc] * scale;
                    if (gj > gi) val = -1e30f;
                    Ss[(srg + rr) * SPAD + scg + cc] = val;
                }
        }
        __syncthreads();

        // online softmax: warp w handles rows w*8..w*8+7; lane = col
        {
            int w = tid >> 5, lane = tid & 31;
            for (int rr = 0; rr < 8; rr++) {
                int r = w * 8 + rr;
                float v = Ss[r * SPAD + lane];
                float mx = v;
#pragma unroll
                for (int off = 16; off; off >>= 1) mx = fmaxf(mx, __shfl_xor_sync(0xffffffffu, mx, off));
                float mo = m_s[r];
                float mn = fmaxf(mo, mx);
                float p = __expf(v - mn);
                Ss[r * SPAD + lane] = p;
                float su = p;
#pragma unroll
                for (int off = 16; off; off >>= 1) su += __shfl_xor_sync(0xffffffffu, su, off);
                if (lane == 0) {
                    float al = __expf(mo - mn);
                    a_s[r] = al;
                    l_s[r] = l_s[r] * al + su;
                    m_s[r] = mn;
                }
            }
        }
        __syncthreads();

        // O += P @ V
        {
            float al0 = a_s[r0], al1 = a_s[r0 + 1];
#pragma unroll
            for (int j = 0; j < 32; j++) { acc0[j] *= al0; acc1[j] *= al1; }
            for (int j = 0; j < 32; j++) {
                float p0 = Ss[r0 * SPAD + j];
                float p1 = Ss[(r0 + 1) * SPAD + j];
#pragma unroll
                for (int cc = 0; cc < 32; cc += 4) {
                    float4 vv = *(const float4*)&Vs[j * VPAD + c0 + cc];
                    acc0[cc + 0] += p0 * vv.x; acc0[cc + 1] += p0 * vv.y;
                    acc0[cc + 2] += p0 * vv.z; acc0[cc + 3] += p0 * vv.w;
                    acc1[cc + 0] += p1 * vv.x; acc1[cc + 1] += p1 * vv.y;
                    acc1[cc + 2] += p1 * vv.z; acc1[cc + 3] += p1 * vv.w;
                }
            }
        }
    }
    __syncthreads();
    float li0 = 1.f / l_s[r0];
    float li1 = 1.f / l_s[r0 + 1];
#pragma unroll
    for (int cc = 0; cc < 32; cc++) {
        olat[(long)(i0 + r0)     * (H_ * KVLORA_) + h * KVLORA_ + c0 + cc] = acc0[cc] * li0;
        olat[(long)(i0 + r0 + 1) * (H_ * KVLORA_) + h * KVLORA_ + c0 + cc] = acc1[cc] * li1;
    }
}

// ---------------- host ----------------
extern "C" void kernel_launch(void* const* d_in, const int* in_sizes, int n_in,
                              void* d_out, int out_size)
{
    const int*   positions = (const int*)  d_in[0];
    const float* hidden    = (const float*)d_in[1];
    const float* w_qa      = (const float*)d_in[2];
    const float* g_qa      = (const float*)d_in[3];
    const float* w_qb      = (const float*)d_in[4];
    const float* w_kva     = (const float*)d_in[5];
    const float* g_kva     = (const float*)d_in[6];
    const float* w_kc      = (const float*)d_in[7];
    const float* w_vc      = (const float*)d_in[8];
    const float* w_o       = (const float*)d_in[9];
    float* out = (float*)d_out;

    float *qa, *qan, *q, *lat, *kin, *qin, *olat, *ov;
    cudaGetSymbolAddress((void**)&qa,   sc_qa);
    cudaGetSymbolAddress((void**)&qan,  sc_qan);
    cudaGetSymbolAddress((void**)&q,    sc_q);
    cudaGetSymbolAddress((void**)&lat,  sc_lat);
    cudaGetSymbolAddress((void**)&kin,  sc_kin);
    cudaGetSymbolAddress((void**)&qin,  sc_qin);
    cudaGetSymbolAddress((void**)&olat, sc_olat);
    cudaGetSymbolAddress((void**)&ov,   sc_ov);

    cudaFuncSetAttribute(attn_kernel, cudaFuncAttributeMaxDynamicSharedMemorySize, ATTN_SMEM);

    dim3 thr(256);

    // 1) qa = hidden @ w_qa   [2048,768]
    sgemm128<<<dim3(QLORA_/128, T_/128, 1), thr>>>(hidden, w_qa, qa,
        T_, QLORA_, HID_, HID_, QLORA_, QLORA_, 0, 0, 0);
    // 2) rmsnorm
    rms768_kernel<<<T_, thr>>>(qa, g_qa, qan);
    // 3) q = qan @ w_qb       [2048,3840]
    sgemm128<<<dim3((H_*QHD)/128, T_/128, 1), thr>>>(qan, w_qb, q,
        T_, H_*QHD, QLORA_, QLORA_, H_*QHD, H_*QHD, 0, 0, 0);
    // 4) latent = hidden @ w_kva  [2048,288]
    sgemm128<<<dim3((DQK+127)/128, T_/128, 1), thr>>>(hidden, w_kva, lat,
        T_, DQK, HID_, HID_, DQK, DQK, 0, 0, 0);
    // 5) k_in build (rmsnorm + rope)
    latent_kernel<<<T_, thr>>>(lat, g_kva, positions, kin);
    // 6) q_lat = q_nope @ w_kc[h] (batched over heads) -> qin[:, h, 0:256]
    sgemm128<<<dim3(KVLORA_/128, T_/128, H_), thr>>>(q, w_kc, qin,
        T_, KVLORA_, NOPE_, H_*QHD, KVLORA_, H_*DQK,
        (long)QHD, (long)NOPE_*KVLORA_, (long)DQK);
    // 7) rope q_pe -> qin[:, h, 256:288]
    rope_q_kernel<<<(T_*H_*16 + 255)/256, thr>>>(q, positions, qin);
    // 8) attention -> olat [T,H,256]
    attn_kernel<<<dim3(T_/64, H_), thr, ATTN_SMEM>>>(qin, kin, olat);
    // 9) ov[:, h*64:...] = olat[:,h,:] @ w_vc[h]  (batched)
    sgemm128<<<dim3(1, T_/128, H_), thr>>>(olat, w_vc, ov,
        T_, VDIM_, KVLORA_, H_*KVLORA_, VDIM_, H_*VDIM_,
        (long)KVLORA_, (long)KVLORA_*VDIM_, (long)VDIM_);
    // 10) out = ov @ w_o     [2048,2560]
    sgemm128<<<dim3(HID_/128, T_/128, 1), thr>>>(ov, w_o, out,
        T_, HID_, H_*VDIM_, H_*VDIM_, HID_, HID_, 0, 0, 0);
}

// round 2
// speedup vs baseline: 1.1388x; 1.1388x over previous
#include <cuda_runtime.h>
#include <math.h>

#define T_      2048
#define HID_    2560
#define H_      40
#define NOPE_   64
#define ROPE_   32
#define VDIM_   64
#define QLORA_  768
#define KVLORA_ 256
#define DQK     288
#define QHD     96
#define EPS_    1e-5f

// ---------------- scratch ----------------
__device__ float sc_qa  [T_ * QLORA_];
__device__ float sc_qan [T_ * QLORA_];
__device__ float sc_q   [T_ * H_ * QHD];
__device__ float sc_lat [T_ * DQK];
__device__ float sc_kin [T_ * DQK];
__device__ float sc_qin [(size_t)T_ * H_ * DQK];
__device__ float sc_olat[(size_t)T_ * H_ * KVLORA_];
__device__ float sc_ov  [T_ * H_ * VDIM_];

// ---------------- double-buffered SGEMM 128x128x16 ----------------
__global__ void __launch_bounds__(256, 2)
sgemm_db(const float* __restrict__ A, const float* __restrict__ B,
         float* __restrict__ C,
         int M, int N, int K, int lda, int ldb, int ldc,
         long sA, long sB, long sC)
{
    __shared__ float As[2][16][128];
    __shared__ float Bs[2][16][132];

    const float* Ab = A + (long)blockIdx.z * sA;
    const float* Bb = B + (long)blockIdx.z * sB;
    float*       Cb = C + (long)blockIdx.z * sC;

    const int bm0 = blockIdx.y * 128;
    const int bn0 = blockIdx.x * 128;
    const int tid = threadIdx.x;
    const int tx  = tid & 15;
    const int ty  = tid >> 4;

    // A: row = tid>>1 (128 rows), k = (tid&1)*8 + {0..7}
    const int a_row = tid >> 1;
    const int a_k   = (tid & 1) * 8;
    // B: k = tid>>5 (+8), col = (tid&31)*4
    const int b_k   = tid >> 5;
    const int b_col = (tid & 31) * 4;
    const bool bvalid = (bn0 + b_col) < N;

    float acc[8][8];
#pragma unroll
    for (int i = 0; i < 8; i++)
#pragma unroll
        for (int j = 0; j < 8; j++) acc[i][j] = 0.f;

    const int nc = K / 16;

    // prologue: chunk 0 -> smem[0]
    {
        const float* ap = Ab + (long)(bm0 + a_row) * lda + a_k;
        float4 a0 = *(const float4*)(ap);
        float4 a1 = *(const float4*)(ap + 4);
        As[0][a_k + 0][a_row] = a0.x; As[0][a_k + 1][a_row] = a0.y;
        As[0][a_k + 2][a_row] = a0.z; As[0][a_k + 3][a_row] = a0.w;
        As[0][a_k + 4][a_row] = a1.x; As[0][a_k + 5][a_row] = a1.y;
        As[0][a_k + 6][a_row] = a1.z; As[0][a_k + 7][a_row] = a1.w;
        float4 z4 = make_float4(0.f, 0.f, 0.f, 0.f);
        float4 b0 = bvalid ? *(const float4*)(Bb + (long)b_k * ldb + bn0 + b_col) : z4;
        float4 b1 = bvalid ? *(const float4*)(Bb + (long)(b_k + 8) * ldb + bn0 + b_col) : z4;
        *(float4*)&Bs[0][b_k][b_col]     = b0;
        *(float4*)&Bs[0][b_k + 8][b_col] = b1;
    }
    __syncthreads();

    int buf = 0;
    for (int c = 0; c < nc; c++) {
        float4 a0, a1, b0, b1;
        const bool more = (c + 1 < nc);
        if (more) {
            const int k0 = (c + 1) * 16;
            const float* ap = Ab + (long)(bm0 + a_row) * lda + k0 + a_k;
            a0 = *(const float4*)(ap);
            a1 = *(const float4*)(ap + 4);
            float4 z4 = make_float4(0.f, 0.f, 0.f, 0.f);
            b0 = bvalid ? *(const float4*)(Bb + (long)(k0 + b_k) * ldb + bn0 + b_col) : z4;
            b1 = bvalid ? *(const float4*)(Bb + (long)(k0 + b_k + 8) * ldb + bn0 + b_col) : z4;
        }

#pragma unroll
        for (int kk = 0; kk < 16; kk++) {
            float4 av0 = *(const float4*)&As[buf][kk][ty * 8];
            float4 av1 = *(const float4*)&As[buf][kk][ty * 8 + 4];
            float4 bv0 = *(const float4*)&Bs[buf][kk][tx * 8];
            float4 bv1 = *(const float4*)&Bs[buf][kk][tx * 8 + 4];
            float av[8] = {av0.x, av0.y, av0.z, av0.w, av1.x, av1.y, av1.z, av1.w};
            float bv[8] = {bv0.x, bv0.y, bv0.z, bv0.w, bv1.x, bv1.y, bv1.z, bv1.w};
#pragma unroll
            for (int i = 0; i < 8; i++)
#pragma unroll
                for (int j = 0; j < 8; j++) acc[i][j] += av[i] * bv[j];
        }

        if (more) {
            const int nb = buf ^ 1;
            As[nb][a_k + 0][a_row] = a0.x; As[nb][a_k + 1][a_row] = a0.y;
            As[nb][a_k + 2][a_row] = a0.z; As[nb][a_k + 3][a_row] = a0.w;
            As[nb][a_k + 4][a_row] = a1.x; As[nb][a_k + 5][a_row] = a1.y;
            As[nb][a_k + 6][a_row] = a1.z; As[nb][a_k + 7][a_row] = a1.w;
            *(float4*)&Bs[nb][b_k][b_col]     = b0;
            *(float4*)&Bs[nb][b_k + 8][b_col] = b1;
        }
        __syncthreads();
        buf ^= 1;
    }

#pragma unroll
    for (int i = 0; i < 8; i++) {
        const int gr = bm0 + ty * 8 + i;
#pragma unroll
        for (int j = 0; j < 8; j += 4) {
            const int gn = bn0 + tx * 8 + j;
            if (gn < N) {
                float4 v = make_float4(acc[i][j], acc[i][j + 1], acc[i][j + 2], acc[i][j + 3]);
                *(float4*)(Cb + (long)gr * ldc + gn) = v;
            }
        }
    }
}

// ---------------- RMSNorm over 768 ----------------
__global__ void rms768_kernel(const float* __restrict__ in, const float* __restrict__ g,
                              float* __restrict__ out)
{
    int t = blockIdx.x;
    const float* x = in + (long)t * QLORA_;
    int tid = threadIdx.x;
    __shared__ float red[256];
    float s = 0.f;
    for (int i = tid; i < QLORA_; i += 256) { float v = x[i]; s += v * v; }
    red[tid] = s;
    __syncthreads();
    for (int st = 128; st > 0; st >>= 1) { if (tid < st) red[tid] += red[tid + st]; __syncthreads(); }
    __shared__ float rinv;
    if (tid == 0) rinv = rsqrtf(red[0] / (float)QLORA_ + EPS_);
    __syncthreads();
    for (int i = tid; i < QLORA_; i += 256)
        out[(long)t * QLORA_ + i] = x[i] * rinv * g[i];
}

// ---------------- latent -> k_in ----------------
__global__ void latent_kernel(const float* __restrict__ lat, const float* __restrict__ g,
                              const int* __restrict__ pos, float* __restrict__ kin)
{
    int t = blockIdx.x;
    const float* x = lat + (long)t * DQK;
    int tid = threadIdx.x;
    __shared__ float red[256];
    float v = x[tid];
    red[tid] = v * v;
    __syncthreads();
    for (int st = 128; st > 0; st >>= 1) { if (tid < st) red[tid] += red[tid + st]; __syncthreads(); }
    __shared__ float rinv;
    if (tid == 0) rinv = rsqrtf(red[0] / (float)KVLORA_ + EPS_);
    __syncthreads();
    kin[(long)t * DQK + tid] = v * rinv * g[tid];
    if (tid < 16) {
        float p = (float)pos[t];
        float f = p * powf(10000.f, -(float)tid / 16.f);
        float c = cosf(f), s = sinf(f);
        float x1 = x[KVLORA_ + tid];
        float x2 = x[KVLORA_ + 16 + tid];
        kin[(long)t * DQK + KVLORA_ + tid]      = x1 * c - x2 * s;
        kin[(long)t * DQK + KVLORA_ + 16 + tid] = x2 * c + x1 * s;
    }
}

// ---------------- RoPE q_pe ----------------
__global__ void rope_q_kernel(const float* __restrict__ q, const int* __restrict__ pos,
                              float* __restrict__ qin)
{
    int idx = blockIdx.x * blockDim.x + threadIdx.x;
    if (idx >= T_ * H_ * 16) return;
    int j = idx & 15;
    int h = (idx >> 4) % H_;
    int t = idx / (16 * H_);
    float p = (float)pos[t];
    float f = p * powf(10000.f, -(float)j / 16.f);
    float c = cosf(f), s = sinf(f);
    const float* qp = q + (long)t * (H_ * QHD) + h * QHD + NOPE_;
    float x1 = qp[j], x2 = qp[16 + j];
    float* o = qin + (long)t * (H_ * DQK) + h * DQK + KVLORA_;
    o[j]      = x1 * c - x2 * s;
    o[16 + j] = x2 * c + x1 * s;
}

// ---------------- flash attention v2: register S/P softmax ----------------
#define ABM 64
#define ABN 32
#define KSP 36
#define VSP 260
#define PSP 36
#define ATTN_SMEM ((288 * 64 + 288 * KSP + 32 * VSP + 64 * PSP) * 4)

__global__ void __launch_bounds__(256, 1)
attn2_kernel(const float* __restrict__ qin, const float* __restrict__ kin,
             float* __restrict__ olat)
{
    extern __shared__ float sm[];
    float* Qs = sm;                    // [288][64] k-major
    float* Ks = Qs + 288 * 64;         // [288][36] k-major
    float* Vs = Ks + 288 * KSP;        // [32][260] row-major
    float* Ps = Vs + 32 * VSP;         // [64][36]  row-major

    const int h   = blockIdx.y;
    const int qb  = gridDim.x - 1 - blockIdx.x;   // heavy blocks first
    const int i0  = qb * ABM;
    const int tid = threadIdx.x;
    const int tx  = tid & 7;            // S col group (4 cols)
    const int ty  = tid >> 3;           // S row group (2 rows), 0..31

    // load Q transposed into Qs[k][row]
    {
        const int row   = tid >> 2;
        const int dbase = (tid & 3) * 72;
        const float* src = qin + (size_t)(i0 + row) * (H_ * DQK) + h * DQK + dbase;
#pragma unroll
        for (int i = 0; i < 18; i++) {
            float4 v = *(const float4*)(src + i * 4);
            const int d = dbase + i * 4;
            Qs[(d + 0) * 64 + row] = v.x;
            Qs[(d + 1) * 64 + row] = v.y;
            Qs[(d + 2) * 64 + row] = v.z;
            Qs[(d + 3) * 64 + row] = v.w;
        }
    }

    float o0[32], o1[32];
#pragma unroll
    for (int i = 0; i < 32; i++) { o0[i] = 0.f; o1[i] = 0.f; }
    float m0 = -1e30f, m1 = -1e30f, l0 = 0.f, l1 = 0.f;

    const float scale = 0.102062072615966f;  // 1/sqrt(96)
    const int gi0 = i0 + ty * 2;
    const int nkb = 2 * qb + 2;

    for (int kb = 0; kb < nkb; kb++) {
        const int j0 = kb * ABN;
        __syncthreads();
        // K transposed + V row-major
        {
            const int row   = tid >> 3;
            const int dbase = tx * 36;
            const float* src = kin + (size_t)(j0 + row) * DQK + dbase;
#pragma unroll
            for (int i = 0; i < 9; i++) {
                float4 v = *(const float4*)(src + i * 4);
                const int d = dbase + i * 4;
                Ks[(d + 0) * KSP + row] = v.x;
                Ks[(d + 1) * KSP + row] = v.y;
                Ks[(d + 2) * KSP + row] = v.z;
                Ks[(d + 3) * KSP + row] = v.w;
            }
            const float* vsrc = kin + (size_t)(j0 + row) * DQK + tx * 32;
            float* vdst = &Vs[row * VSP + tx * 32];
#pragma unroll
            for (int i = 0; i < 8; i++)
                *(float4*)(vdst + i * 4) = *(const float4*)(vsrc + i * 4);
        }
        __syncthreads();

        // S = Q K^T : 2x4 per thread
        float s00 = 0.f, s01 = 0.f, s02 = 0.f, s03 = 0.f;
        float s10 = 0.f, s11 = 0.f, s12 = 0.f, s13 = 0.f;
        const float* qp = &Qs[ty * 2];
        const float* kp = &Ks[tx * 4];
#pragma unroll 8
        for (int kk = 0; kk < DQK; kk++) {
            float2 qv = *(const float2*)(qp + kk * 64);
            float4 kv = *(const float4*)(kp + kk * KSP);
            s00 += qv.x * kv.x; s01 += qv.x * kv.y; s02 += qv.x * kv.z; s03 += qv.x * kv.w;
            s10 += qv.y * kv.x; s11 += qv.y * kv.y; s12 += qv.y * kv.z; s13 += qv.y * kv.w;
        }

        // scale + causal mask
        {
            const int gj = j0 + tx * 4;
            const int g0 = gi0, g1 = gi0 + 1;
            s00 = (gj + 0 <= g0) ? s00 * scale : -1e30f;
            s01 = (gj + 1 <= g0) ? s01 * scale : -1e30f;
            s02 = (gj + 2 <= g0) ? s02 * scale : -1e30f;
            s03 = (gj + 3 <= g0) ? s03 * scale : -1e30f;
            s10 = (gj + 0 <= g1) ? s10 * scale : -1e30f;
            s11 = (gj + 1 <= g1) ? s11 * scale : -1e30f;
            s12 = (gj + 2 <= g1) ? s12 * scale : -1e30f;
            s13 = (gj + 3 <= g1) ? s13 * scale : -1e30f;
        }

        // online softmax, rows in registers (8-lane row groups)
        {
            float mx = fmaxf(fmaxf(s00, s01), fmaxf(s02, s03));
            mx = fmaxf(mx, __shfl_xor_sync(0xffffffffu, mx, 1));
            mx = fmaxf(mx, __shfl_xor_sync(0xffffffffu, mx, 2));
            mx = fmaxf(mx, __shfl_xor_sync(0xffffffffu, mx, 4));
            float mn = fmaxf(m0, mx);
            float al = __expf(m0 - mn);
            float p0 = __expf(s00 - mn), p1 = __expf(s01 - mn);
            float p2 = __expf(s02 - mn), p3 = __expf(s03 - mn);
            float su = p0 + p1 + p2 + p3;
            su += __shfl_xor_sync(0xffffffffu, su, 1);
            su += __shfl_xor_sync(0xffffffffu, su, 2);
            su += __shfl_xor_sync(0xffffffffu, su, 4);
            l0 = l0 * al + su; m0 = mn;
#pragma unroll
            for (int i = 0; i < 32; i++) o0[i] *= al;
            *(float4*)&Ps[(ty * 2) * PSP + tx * 4] = make_float4(p0, p1, p2, p3);
        }
        {
            float mx = fmaxf(fmaxf(s10, s11), fmaxf(s12, s13));
            mx = fmaxf(mx, __shfl_xor_sync(0xffffffffu, mx, 1));
            mx = fmaxf(mx, __shfl_xor_sync(0xffffffffu, mx, 2));
            mx = fmaxf(mx, __shfl_xor_sync(0xffffffffu, mx, 4));
            float mn = fmaxf(m1, mx);
            float al = __expf(m1 - mn);
            float p0 = __expf(s10 - mn), p1 = __expf(s11 - mn);
            float p2 = __expf(s12 - mn), p3 = __expf(s13 - mn);
            float su = p0 + p1 + p2 + p3;
            su += __shfl_xor_sync(0xffffffffu, su, 1);
            su += __shfl_xor_sync(0xffffffffu, su, 2);
            su += __shfl_xor_sync(0xffffffffu, su, 4);
            l1 = l1 * al + su; m1 = mn;
#pragma unroll
            for (int i = 0; i < 32; i++) o1[i] *= al;
            *(float4*)&Ps[(ty * 2 + 1) * PSP + tx * 4] = make_float4(p0, p1, p2, p3);
        }
        __syncwarp();

        // O += P @ V
        const float* pr0 = &Ps[(ty * 2) * PSP];
        const float* pr1 = &Ps[(ty * 2 + 1) * PSP];
        const float* vb  = &Vs[tx * 32];
#pragma unroll 4
        for (int kk = 0; kk < ABN; kk++) {
            float p0 = pr0[kk];
            float p1 = pr1[kk];
            const float4* vp = (const float4*)(vb + kk * VSP);
#pragma unroll
            for (int i = 0; i < 8; i++) {
                float4 v = vp[i];
                o0[i * 4 + 0] += p0 * v.x; o0[i * 4 + 1] += p0 * v.y;
                o0[i * 4 + 2] += p0 * v.z; o0[i * 4 + 3] += p0 * v.w;
                o1[i * 4 + 0] += p1 * v.x; o1[i * 4 + 1] += p1 * v.y;
                o1[i * 4 + 2] += p1 * v.z; o1[i * 4 + 3] += p1 * v.w;
            }
        }
    }

    const float li0 = 1.f / l0;
    const float li1 = 1.f / l1;
    float* d0 = olat + (size_t)(gi0)     * (H_ * KVLORA_) + h * KVLORA_ + tx * 32;
    float* d1 = olat + (size_t)(gi0 + 1) * (H_ * KVLORA_) + h * KVLORA_ + tx * 32;
#pragma unroll
    for (int i = 0; i < 8; i++) {
        *(float4*)(d0 + i * 4) = make_float4(o0[i*4] * li0, o0[i*4+1] * li0, o0[i*4+2] * li0, o0[i*4+3] * li0);
        *(float4*)(d1 + i * 4) = make_float4(o1[i*4] * li1, o1[i*4+1] * li1, o1[i*4+2] * li1, o1[i*4+3] * li1);
    }
}

// ---------------- host ----------------
extern "C" void kernel_launch(void* const* d_in, const int* in_sizes, int n_in,
                              void* d_out, int out_size)
{
    const int*   positions = (const int*)  d_in[0];
    const float* hidden    = (const float*)d_in[1];
    const float* w_qa      = (const float*)d_in[2];
    const float* g_qa      = (const float*)d_in[3];
    const float* w_qb      = (const float*)d_in[4];
    const float* w_kva     = (const float*)d_in[5];
    const float* g_kva     = (const float*)d_in[6];
    const float* w_kc      = (const float*)d_in[7];
    const float* w_vc      = (const float*)d_in[8];
    const float* w_o       = (const float*)d_in[9];
    float* out = (float*)d_out;

    float *qa, *qan, *q, *lat, *kin, *qin, *olat, *ov;
    cudaGetSymbolAddress((void**)&qa,   sc_qa);
    cudaGetSymbolAddress((void**)&qan,  sc_qan);
    cudaGetSymbolAddress((void**)&q,    sc_q);
    cudaGetSymbolAddress((void**)&lat,  sc_lat);
    cudaGetSymbolAddress((void**)&kin,  sc_kin);
    cudaGetSymbolAddress((void**)&qin,  sc_qin);
    cudaGetSymbolAddress((void**)&olat, sc_olat);
    cudaGetSymbolAddress((void**)&ov,   sc_ov);

    cudaFuncSetAttribute(attn2_kernel, cudaFuncAttributeMaxDynamicSharedMemorySize, ATTN_SMEM);

    dim3 thr(256);

    // 1) qa = hidden @ w_qa
    sgemm_db<<<dim3(QLORA_/128, T_/128, 1), thr>>>(hidden, w_qa, qa,
        T_, QLORA_, HID_, HID_, QLORA_, QLORA_, 0, 0, 0);
    // 2) rmsnorm
    rms768_kernel<<<T_, thr>>>(qa, g_qa, qan);
    // 3) q = qan @ w_qb
    sgemm_db<<<dim3((H_*QHD)/128, T_/128, 1), thr>>>(qan, w_qb, q,
        T_, H_*QHD, QLORA_, QLORA_, H_*QHD, H_*QHD, 0, 0, 0);
    // 4) latent = hidden @ w_kva
    sgemm_db<<<dim3((DQK+127)/128, T_/128, 1), thr>>>(hidden, w_kva, lat,
        T_, DQK, HID_, HID_, DQK, DQK, 0, 0, 0);
    // 5) k_in build
    latent_kernel<<<T_, thr>>>(lat, g_kva, positions, kin);
    // 6) q_lat batched over heads
    sgemm_db<<<dim3(KVLORA_/128, T_/128, H_), thr>>>(q, w_kc, qin,
        T_, KVLORA_, NOPE_, H_*QHD, KVLORA_, H_*DQK,
        (long)QHD, (long)NOPE_*KVLORA_, (long)DQK);
    // 7) rope q_pe
    rope_q_kernel<<<(T_*H_*16 + 255)/256, thr>>>(q, positions, qin);
    // 8) attention
    attn2_kernel<<<dim3(T_/ABM, H_), thr, ATTN_SMEM>>>(qin, kin, olat);
    // 9) v-proj batched
    sgemm_db<<<dim3(1, T_/128, H_), thr>>>(olat, w_vc, ov,
        T_, VDIM_, KVLORA_, H_*KVLORA_, VDIM_, H_*VDIM_,
        (long)KVLORA_, (long)KVLORA_*VDIM_, (long)VDIM_);
    // 10) out = ov @ w_o
    sgemm_db<<<dim3(HID_/128, T_/128, 1), thr>>>(ov, w_o, out,
        T_, HID_, H_*VDIM_, H_*VDIM_, HID_, HID_, 0, 0, 0);
}

// round 3
// speedup vs baseline: 4.7364x; 4.1590x over previous
#include <cuda_runtime.h>
#include <math.h>

#define T_      2048
#define HID_    2560
#define H_      40
#define NOPE_   64
#define ROPE_   32
#define VDIM_   64
#define QLORA_  768
#define KVLORA_ 256
#define DQK     288
#define QHD     96
#define EPS_    1e-5f

// ---------------- scratch ----------------
__device__ float sc_qa  [T_ * QLORA_];
__device__ float sc_qan [T_ * QLORA_];
__device__ float sc_q   [T_ * H_ * QHD];
__device__ float sc_lat [T_ * DQK];
__device__ float sc_kin [T_ * DQK];
__device__ float sc_qin [(size_t)T_ * H_ * DQK];
__device__ float sc_olat[(size_t)T_ * H_ * KVLORA_];
__device__ float sc_ov  [T_ * H_ * VDIM_];

// ---------------- tf32 helpers ----------------
__device__ __forceinline__ unsigned tf32c(float x) {
    unsigned u;
    asm("cvt.rna.tf32.f32 %0, %1;" : "=r"(u) : "f"(x));
    return u;
}
__device__ __forceinline__ void mma8(float c[4], const unsigned a[4], unsigned b0, unsigned b1) {
    asm volatile(
        "mma.sync.aligned.m16n8k8.row.col.f32.tf32.tf32.f32 "
        "{%0,%1,%2,%3},{%4,%5,%6,%7},{%8,%9},{%0,%1,%2,%3};\n"
        : "+f"(c[0]), "+f"(c[1]), "+f"(c[2]), "+f"(c[3])
        : "r"(a[0]), "r"(a[1]), "r"(a[2]), "r"(a[3]), "r"(b0), "r"(b1));
}

// ---------------- double-buffered SGEMM 128x128x16 ----------------
__global__ void __launch_bounds__(256, 2)
sgemm_db(const float* __restrict__ A, const float* __restrict__ B,
         float* __restrict__ C,
         int M, int N, int K, int lda, int ldb, int ldc,
         long sA, long sB, long sC)
{
    __shared__ float As[2][16][128];
    __shared__ float Bs[2][16][132];

    const float* Ab = A + (long)blockIdx.z * sA;
    const float* Bb = B + (long)blockIdx.z * sB;
    float*       Cb = C + (long)blockIdx.z * sC;

    const int bm0 = blockIdx.y * 128;
    const int bn0 = blockIdx.x * 128;
    const int tid = threadIdx.x;
    const int tx  = tid & 15;
    const int ty  = tid >> 4;

    const int a_row = tid >> 1;
    const int a_k   = (tid & 1) * 8;
    const int b_k   = tid >> 5;
    const int b_col = (tid & 31) * 4;
    const bool bvalid = (bn0 + b_col) < N;

    float acc[8][8];
#pragma unroll
    for (int i = 0; i < 8; i++)
#pragma unroll
        for (int j = 0; j < 8; j++) acc[i][j] = 0.f;

    const int nc = K / 16;

    {
        const float* ap = Ab + (long)(bm0 + a_row) * lda + a_k;
        float4 a0 = *(const float4*)(ap);
        float4 a1 = *(const float4*)(ap + 4);
        As[0][a_k + 0][a_row] = a0.x; As[0][a_k + 1][a_row] = a0.y;
        As[0][a_k + 2][a_row] = a0.z; As[0][a_k + 3][a_row] = a0.w;
        As[0][a_k + 4][a_row] = a1.x; As[0][a_k + 5][a_row] = a1.y;
        As[0][a_k + 6][a_row] = a1.z; As[0][a_k + 7][a_row] = a1.w;
        float4 z4 = make_float4(0.f, 0.f, 0.f, 0.f);
        float4 b0 = bvalid ? *(const float4*)(Bb + (long)b_k * ldb + bn0 + b_col) : z4;
        float4 b1 = bvalid ? *(const float4*)(Bb + (long)(b_k + 8) * ldb + bn0 + b_col) : z4;
        *(float4*)&Bs[0][b_k][b_col]     = b0;
        *(float4*)&Bs[0][b_k + 8][b_col] = b1;
    }
    __syncthreads();

    int buf = 0;
    for (int c = 0; c < nc; c++) {
        float4 a0, a1, b0, b1;
        const bool more = (c + 1 < nc);
        if (more) {
            const int k0 = (c + 1) * 16;
            const float* ap = Ab + (long)(bm0 + a_row) * lda + k0 + a_k;
            a0 = *(const float4*)(ap);
            a1 = *(const float4*)(ap + 4);
            float4 z4 = make_float4(0.f, 0.f, 0.f, 0.f);
            b0 = bvalid ? *(const float4*)(Bb + (long)(k0 + b_k) * ldb + bn0 + b_col) : z4;
            b1 = bvalid ? *(const float4*)(Bb + (long)(k0 + b_k + 8) * ldb + bn0 + b_col) : z4;
        }

#pragma unroll
        for (int kk = 0; kk < 16; kk++) {
            float4 av0 = *(const float4*)&As[buf][kk][ty * 8];
            float4 av1 = *(const float4*)&As[buf][kk][ty * 8 + 4];
            float4 bv0 = *(const float4*)&Bs[buf][kk][tx * 8];
            float4 bv1 = *(const float4*)&Bs[buf][kk][tx * 8 + 4];
            float av[8] = {av0.x, av0.y, av0.z, av0.w, av1.x, av1.y, av1.z, av1.w};
            float bv[8] = {bv0.x, bv0.y, bv0.z, bv0.w, bv1.x, bv1.y, bv1.z, bv1.w};
#pragma unroll
            for (int i = 0; i < 8; i++)
#pragma unroll
                for (int j = 0; j < 8; j++) acc[i][j] += av[i] * bv[j];
        }

        if (more) {
            const int nb = buf ^ 1;
            As[nb][a_k + 0][a_row] = a0.x; As[nb][a_k + 1][a_row] = a0.y;
            As[nb][a_k + 2][a_row] = a0.z; As[nb][a_k + 3][a_row] = a0.w;
            As[nb][a_k + 4][a_row] = a1.x; As[nb][a_k + 5][a_row] = a1.y;
            As[nb][a_k + 6][a_row] = a1.z; As[nb][a_k + 7][a_row] = a1.w;
            *(float4*)&Bs[nb][b_k][b_col]     = b0;
            *(float4*)&Bs[nb][b_k + 8][b_col] = b1;
        }
        __syncthreads();
        buf ^= 1;
    }

#pragma unroll
    for (int i = 0; i < 8; i++) {
        const int gr = bm0 + ty * 8 + i;
#pragma unroll
        for (int j = 0; j < 8; j += 4) {
            const int gn = bn0 + tx * 8 + j;
            if (gn < N) {
                float4 v = make_float4(acc[i][j], acc[i][j + 1], acc[i][j + 2], acc[i][j + 3]);
                *(float4*)(Cb + (long)gr * ldc + gn) = v;
            }
        }
    }
}

// ---------------- RMSNorm over 768 ----------------
__global__ void rms768_kernel(const float* __restrict__ in, const float* __restrict__ g,
                              float* __restrict__ out)
{
    int t = blockIdx.x;
    const float* x = in + (long)t * QLORA_;
    int tid = threadIdx.x;
    __shared__ float red[256];
    float s = 0.f;
    for (int i = tid; i < QLORA_; i += 256) { float v = x[i]; s += v * v; }
    red[tid] = s;
    __syncthreads();
    for (int st = 128; st > 0; st >>= 1) { if (tid < st) red[tid] += red[tid + st]; __syncthreads(); }
    __shared__ float rinv;
    if (tid == 0) rinv = rsqrtf(red[0] / (float)QLORA_ + EPS_);
    __syncthreads();
    for (int i = tid; i < QLORA_; i += 256)
        out[(long)t * QLORA_ + i] = x[i] * rinv * g[i];
}

// ---------------- latent -> k_in ----------------
__global__ void latent_kernel(const float* __restrict__ lat, const float* __restrict__ g,
                              const int* __restrict__ pos, float* __restrict__ kin)
{
    int t = blockIdx.x;
    const float* x = lat + (long)t * DQK;
    int tid = threadIdx.x;
    __shared__ float red[256];
    float v = x[tid];
    red[tid] = v * v;
    __syncthreads();
    for (int st = 128; st > 0; st >>= 1) { if (tid < st) red[tid] += red[tid + st]; __syncthreads(); }
    __shared__ float rinv;
    if (tid == 0) rinv = rsqrtf(red[0] / (float)KVLORA_ + EPS_);
    __syncthreads();
    kin[(long)t * DQK + tid] = v * rinv * g[tid];
    if (tid < 16) {
        float p = (float)pos[t];
        float f = p * powf(10000.f, -(float)tid / 16.f);
        float c = cosf(f), s = sinf(f);
        float x1 = x[KVLORA_ + tid];
        float x2 = x[KVLORA_ + 16 + tid];
        kin[(long)t * DQK + KVLORA_ + tid]      = x1 * c - x2 * s;
        kin[(long)t * DQK + KVLORA_ + 16 + tid] = x2 * c + x1 * s;
    }
}

// ---------------- RoPE q_pe ----------------
__global__ void rope_q_kernel(const float* __restrict__ q, const int* __restrict__ pos,
                              float* __restrict__ qin)
{
    int idx = blockIdx.x * blockDim.x + threadIdx.x;
    if (idx >= T_ * H_ * 16) return;
    int j = idx & 15;
    int h = (idx >> 4) % H_;
    int t = idx / (16 * H_);
    float p = (float)pos[t];
    float f = p * powf(10000.f, -(float)j / 16.f);
    float c = cosf(f), s = sinf(f);
    const float* qp = q + (long)t * (H_ * QHD) + h * QHD + NOPE_;
    float x1 = qp[j], x2 = qp[16 + j];
    float* o = qin + (long)t * (H_ * DQK) + h * DQK + KVLORA_;
    o[j]      = x1 * c - x2 * s;
    o[16 + j] = x2 * c + x1 * s;
}

// ---------------- flash attention v3: tf32 mma.sync ----------------
#define QLD 292
#define KLD 36
#define VLD 264
#define PLD 68
// floats: Qs 64*292 + Ks 2*64*36 + Vs 64*264 + Ps 64*68 + red 512 + ml 128
#define ATTN_SMEM ((64*QLD + 2*64*KLD + 64*VLD + 64*PLD + 512 + 128) * 4)

__global__ void __launch_bounds__(256, 1)
attn3_kernel(const float* __restrict__ qin, const float* __restrict__ kin,
             float* __restrict__ olat)
{
    extern __shared__ float sm[];
    float* Qs     = sm;                      // [64][QLD] tf32
    float* Ks     = Qs + 64 * QLD;           // [2][64][KLD] tf32
    float* Vs     = Ks + 2 * 64 * KLD;       // [64][VLD] tf32
    float* Ps     = Vs + 64 * VLD;           // [64][PLD] tf32
    float* redmax = Ps + 64 * PLD;           // [64][4]
    float* redsum = redmax + 256;            // [64][4]
    float* m_s    = redsum + 256;            // [64]
    float* l_s    = m_s + 64;                // [64]

    const int h   = blockIdx.y;
    const int qb  = gridDim.x - 1 - blockIdx.x;   // heavy first
    const int i0  = qb * 64;
    const int tid = threadIdx.x;
    const int w    = tid >> 5;
    const int lane = tid & 31;
    const int wm   = (w & 1) * 32;      // warp M base (S rows)
    const int wni  = w >> 1;            // warp N index 0..3
    const int wn   = wni * 16;          // warp N base (S cols)
    const int wv   = wni * 64;          // warp V base (O cols)
    const int lq   = lane >> 2;         // group id
    const int lr   = lane & 3;          // thread in group
    const float scale = 0.102062072615966f;  // 1/sqrt(96)

    // ---- load Q, pre-scaled, tf32 ----
    {
        const int row = tid >> 2;
        const int cg  = (tid & 3) * 72;
        const float* src = qin + (size_t)(i0 + row) * (H_ * DQK) + h * DQK + cg;
        unsigned* dst = (unsigned*)(Qs + row * QLD + cg);
#pragma unroll
        for (int i = 0; i < 18; i++) {
            float4 v = *(const float4*)(src + i * 4);
            uint4 u;
            u.x = tf32c(v.x * scale); u.y = tf32c(v.y * scale);
            u.z = tf32c(v.z * scale); u.w = tf32c(v.w * scale);
            *(uint4*)(dst + i * 4) = u;
        }
    }
    if (tid < 64) { m_s[tid] = -1e30f; l_s[tid] = 0.f; }

    float o[2][8][4];
#pragma unroll
    for (int mi = 0; mi < 2; mi++)
#pragma unroll
        for (int ni = 0; ni < 8; ni++)
#pragma unroll
            for (int r = 0; r < 4; r++) o[mi][ni][r] = 0.f;

    const int krow = tid >> 2, kcg = (tid & 3) * 8;
    const int vrow = tid >> 2, vcg = (tid & 3) * 64;
    const int nkb = qb + 1;

    for (int kb = 0; kb < nkb; kb++) {
        const int j0 = kb * 64;
        __syncthreads();   // protect Vs/Ks/Ps reuse

        // ---- V tile + K chunk 0 ----
        {
            const float* vsrc = kin + (size_t)(j0 + vrow) * DQK + vcg;
            unsigned* vdst = (unsigned*)(Vs + vrow * VLD + vcg);
#pragma unroll
            for (int i = 0; i < 16; i++) {
                float4 v = *(const float4*)(vsrc + i * 4);
                uint4 u;
                u.x = tf32c(v.x); u.y = tf32c(v.y); u.z = tf32c(v.z); u.w = tf32c(v.w);
                *(uint4*)(vdst + i * 4) = u;
            }
            const float* ksrc = kin + (size_t)(j0 + krow) * DQK + kcg;
            float4 t0 = *(const float4*)(ksrc);
            float4 t1 = *(const float4*)(ksrc + 4);
            uint4 u0, u1;
            u0.x = tf32c(t0.x); u0.y = tf32c(t0.y); u0.z = tf32c(t0.z); u0.w = tf32c(t0.w);
            u1.x = tf32c(t1.x); u1.y = tf32c(t1.y); u1.z = tf32c(t1.z); u1.w = tf32c(t1.w);
            unsigned* kdst = (unsigned*)(Ks + krow * KLD + kcg);
            *(uint4*)(kdst)     = u0;
            *(uint4*)(kdst + 4) = u1;
        }
        __syncthreads();

        float s[2][2][4];
#pragma unroll
        for (int mi = 0; mi < 2; mi++)
#pragma unroll
            for (int ni = 0; ni < 2; ni++)
#pragma unroll
                for (int r = 0; r < 4; r++) s[mi][ni][r] = 0.f;

        // ---- QK over 9 chunks of 32 (double-buffered) ----
        for (int c = 0; c < 9; c++) {
            uint4 pf0, pf1;
            if (c < 8) {
                const float* ksrc = kin + (size_t)(j0 + krow) * DQK + (c + 1) * 32 + kcg;
                float4 t0 = *(const float4*)(ksrc);
                float4 t1 = *(const float4*)(ksrc + 4);
                pf0.x = tf32c(t0.x); pf0.y = tf32c(t0.y); pf0.z = tf32c(t0.z); pf0.w = tf32c(t0.w);
                pf1.x = tf32c(t1.x); pf1.y = tf32c(t1.y); pf1.z = tf32c(t1.z); pf1.w = tf32c(t1.w);
            }
            const float* kbuf = Ks + (c & 1) * 64 * KLD;
            const int cb = c * 32;
#pragma unroll
            for (int ks = 0; ks < 4; ks++) {
                const int d0 = ks * 8;
                unsigned a[2][4];
#pragma unroll
                for (int mi = 0; mi < 2; mi++) {
                    const unsigned* q0 = (const unsigned*)(Qs + (wm + 16 * mi + lq) * QLD) + cb + d0 + lr;
                    const unsigned* q1 = q0 + 8 * QLD;
                    a[mi][0] = q0[0]; a[mi][1] = q1[0]; a[mi][2] = q0[4]; a[mi][3] = q1[4];
                }
#pragma unroll
                for (int ni = 0; ni < 2; ni++) {
                    const unsigned* kp = (const unsigned*)(kbuf + (wn + 8 * ni + lq) * KLD) + d0 + lr;
                    unsigned b0 = kp[0], b1 = kp[4];
                    mma8(s[0][ni], a[0], b0, b1);
                    mma8(s[1][ni], a[1], b0, b1);
                }
            }
            if (c < 8) {
                unsigned* kdst = (unsigned*)(Ks + ((c + 1) & 1) * 64 * KLD + krow * KLD + kcg);
                *(uint4*)(kdst)     = pf0;
                *(uint4*)(kdst + 4) = pf1;
            }
            __syncthreads();
        }

        // ---- causal mask (diagonal block only) ----
        if (kb == qb) {
#pragma unroll
            for (int mi = 0; mi < 2; mi++)
#pragma unroll
                for (int ni = 0; ni < 2; ni++)
#pragma unroll
                    for (int r = 0; r < 4; r++) {
                        int row = wm + 16 * mi + 8 * (r >> 1) + lq;
                        int col = wn + 8 * ni + 2 * lr + (r & 1);
                        if (col > row) s[mi][ni][r] = -1e30f;
                    }
        }

        // ---- online softmax ----
        float pmax[2][2];
#pragma unroll
        for (int mi = 0; mi < 2; mi++)
#pragma unroll
            for (int half = 0; half < 2; half++) {
                float mx = fmaxf(fmaxf(s[mi][0][2*half], s[mi][0][2*half+1]),
                                 fmaxf(s[mi][1][2*half], s[mi][1][2*half+1]));
                mx = fmaxf(mx, __shfl_xor_sync(0xffffffffu, mx, 1));
                mx = fmaxf(mx, __shfl_xor_sync(0xffffffffu, mx, 2));
                pmax[mi][half] = mx;
                if (lr == 0) redmax[(wm + 16 * mi + 8 * half + lq) * 4 + wni] = mx;
            }
        __syncthreads();

        float alpha[2][2], mnew[2][2], psum[2][2];
#pragma unroll
        for (int mi = 0; mi < 2; mi++)
#pragma unroll
            for (int half = 0; half < 2; half++) {
                const int row = wm + 16 * mi + 8 * half + lq;
                const float* rp = redmax + row * 4;
                float bm = fmaxf(fmaxf(rp[0], rp[1]), fmaxf(rp[2], rp[3]));
                float mo = m_s[row];
                float mn = fmaxf(mo, bm);
                mnew[mi][half]  = mn;
                alpha[mi][half] = __expf(mo - mn);
                float p0[2], p1[2];
#pragma unroll
                for (int ni = 0; ni < 2; ni++) {
                    p0[ni] = __expf(s[mi][ni][2*half]     - mn);
                    p1[ni] = __expf(s[mi][ni][2*half + 1] - mn);
                }
                float su = p0[0] + p1[0] + p0[1] + p1[1];
                su += __shfl_xor_sync(0xffffffffu, su, 1);
                su += __shfl_xor_sync(0xffffffffu, su, 2);
                psum[mi][half] = su;
                if (lr == 0) redsum[row * 4 + wni] = su;
                // store P (tf32) to smem
#pragma unroll
                for (int ni = 0; ni < 2; ni++) {
                    unsigned* pp = (unsigned*)(Ps + row * PLD + wn + 8 * ni + 2 * lr);
                    pp[0] = tf32c(p0[ni]);
                    pp[1] = tf32c(p1[ni]);
                }
            }
        // rescale O by alpha
#pragma unroll
        for (int mi = 0; mi < 2; mi++)
#pragma unroll
            for (int ni = 0; ni < 8; ni++) {
                o[mi][ni][0] *= alpha[mi][0];
                o[mi][ni][1] *= alpha[mi][0];
                o[mi][ni][2] *= alpha[mi][1];
                o[mi][ni][3] *= alpha[mi][1];
            }
        __syncthreads();

        // owner threads update m/l
        if (w < 2 && lr == 0) {
#pragma unroll
            for (int mi = 0; mi < 2; mi++)
#pragma unroll
                for (int half = 0; half < 2; half++) {
                    const int row = wm + 16 * mi + 8 * half + lq;
                    const float* rp = redsum + row * 4;
                    l_s[row] = l_s[row] * alpha[mi][half] + (rp[0] + rp[1] + rp[2] + rp[3]);
                    m_s[row] = mnew[mi][half];
                }
        }

        // ---- O += P @ V ----
#pragma unroll
        for (int kst = 0; kst < 8; kst++) {
            unsigned a[2][4];
#pragma unroll
            for (int mi = 0; mi < 2; mi++) {
                const unsigned* p0 = (const unsigned*)(Ps + (wm + 16 * mi + lq) * PLD) + kst * 8 + lr;
                const unsigned* p1 = p0 + 8 * PLD;
                a[mi][0] = p0[0]; a[mi][1] = p1[0]; a[mi][2] = p0[4]; a[mi][3] = p1[4];
            }
            const unsigned* vrow0 = (const unsigned*)(Vs + (kst * 8 + lr) * VLD);
#pragma unroll
            for (int ni = 0; ni < 8; ni++) {
                unsigned b0 = vrow0[wv + 8 * ni + lq];
                unsigned b1 = vrow0[4 * VLD + wv + 8 * ni + lq];
                mma8(o[0][ni], a[0], b0, b1);
                mma8(o[1][ni], a[1], b0, b1);
            }
        }
    }

    __syncthreads();
    // ---- finalize: divide by l, write out ----
#pragma unroll
    for (int mi = 0; mi < 2; mi++)
#pragma unroll
        for (int half = 0; half < 2; half++) {
            const int row = wm + 16 * mi + 8 * half + lq;
            const float linv = 1.f / l_s[row];
            float* dst = olat + (size_t)(i0 + row) * (H_ * KVLORA_) + h * KVLORA_;
#pragma unroll
            for (int ni = 0; ni < 8; ni++) {
                float2 v = make_float2(o[mi][ni][2*half] * linv, o[mi][ni][2*half + 1] * linv);
                *(float2*)(dst + wv + 8 * ni + 2 * lr) = v;
            }
        }
}

// ---------------- host ----------------
extern "C" void kernel_launch(void* const* d_in, const int* in_sizes, int n_in,
                              void* d_out, int out_size)
{
    const int*   positions = (const int*)  d_in[0];
    const float* hidden    = (const float*)d_in[1];
    const float* w_qa      = (const float*)d_in[2];
    const float* g_qa      = (const float*)d_in[3];
    const float* w_qb      = (const float*)d_in[4];
    const float* w_kva     = (const float*)d_in[5];
    const float* g_kva     = (const float*)d_in[6];
    const float* w_kc      = (const float*)d_in[7];
    const float* w_vc      = (const float*)d_in[8];
    const float* w_o       = (const float*)d_in[9];
    float* out = (float*)d_out;

    float *qa, *qan, *q, *lat, *kin, *qin, *olat, *ov;
    cudaGetSymbolAddress((void**)&qa,   sc_qa);
    cudaGetSymbolAddress((void**)&qan,  sc_qan);
    cudaGetSymbolAddress((void**)&q,    sc_q);
    cudaGetSymbolAddress((void**)&lat,  sc_lat);
    cudaGetSymbolAddress((void**)&kin,  sc_kin);
    cudaGetSymbolAddress((void**)&qin,  sc_qin);
    cudaGetSymbolAddress((void**)&olat, sc_olat);
    cudaGetSymbolAddress((void**)&ov,   sc_ov);

    cudaFuncSetAttribute(attn3_kernel, cudaFuncAttributeMaxDynamicSharedMemorySize, ATTN_SMEM);

    dim3 thr(256);

    // 1) qa = hidden @ w_qa
    sgemm_db<<<dim3(QLORA_/128, T_/128, 1), thr>>>(hidden, w_qa, qa,
        T_, QLORA_, HID_, HID_, QLORA_, QLORA_, 0, 0, 0);
    // 2) rmsnorm
    rms768_kernel<<<T_, thr>>>(qa, g_qa, qan);
    // 3) q = qan @ w_qb
    sgemm_db<<<dim3((H_*QHD)/128, T_/128, 1), thr>>>(qan, w_qb, q,
        T_, H_*QHD, QLORA_, QLORA_, H_*QHD, H_*QHD, 0, 0, 0);
    // 4) latent = hidden @ w_kva
    sgemm_db<<<dim3((DQK+127)/128, T_/128, 1), thr>>>(hidden, w_kva, lat,
        T_, DQK, HID_, HID_, DQK, DQK, 0, 0, 0);
    // 5) k_in build
    latent_kernel<<<T_, thr>>>(lat, g_kva, positions, kin);
    // 6) q_lat batched over heads
    sgemm_db<<<dim3(KVLORA_/128, T_/128, H_), thr>>>(q, w_kc, qin,
        T_, KVLORA_, NOPE_, H_*QHD, KVLORA_, H_*DQK,
        (long)QHD, (long)NOPE_*KVLORA_, (long)DQK);
    // 7) rope q_pe
    rope_q_kernel<<<(T_*H_*16 + 255)/256, thr>>>(q, positions, qin);
    // 8) attention (tf32 mma)
    attn3_kernel<<<dim3(T_/64, H_), thr, ATTN_SMEM>>>(qin, kin, olat);
    // 9) v-proj batched
    sgemm_db<<<dim3(1, T_/128, H_), thr>>>(olat, w_vc, ov,
        T_, VDIM_, KVLORA_, H_*KVLORA_, VDIM_, H_*VDIM_,
        (long)KVLORA_, (long)KVLORA_*VDIM_, (long)VDIM_);
    // 10) out = ov @ w_o
    sgemm_db<<<dim3(HID_/128, T_/128, 1), thr>>>(ov, w_o, out,
        T_, HID_, H_*VDIM_, H_*VDIM_, HID_, HID_, 0, 0, 0);
}

// round 4
// speedup vs baseline: 6.9790x; 1.4735x over previous
#include <cuda_runtime.h>
#include <math.h>

#define T_      2048
#define HID_    2560
#define H_      40
#define NOPE_   64
#define ROPE_   32
#define VDIM_   64
#define QLORA_  768
#define KVLORA_ 256
#define DQK     288
#define QHD     96
#define EPS_    1e-5f

// ---------------- scratch ----------------
__device__ float sc_qa  [T_ * QLORA_];
__device__ float sc_qan [T_ * QLORA_];
__device__ float sc_q   [T_ * H_ * QHD];
__device__ float sc_lat [T_ * DQK];
__device__ float sc_kin [T_ * DQK];
__device__ float sc_qin [(size_t)T_ * H_ * DQK];
__device__ float sc_olat[(size_t)T_ * H_ * KVLORA_];
__device__ float sc_ov  [T_ * H_ * VDIM_];

// ---------------- tf32 helpers ----------------
__device__ __forceinline__ unsigned tf32c(float x) {
    unsigned u;
    asm("cvt.rna.tf32.f32 %0, %1;" : "=r"(u) : "f"(x));
    return u;
}
__device__ __forceinline__ float tf32f(float x) {
    return __uint_as_float(tf32c(x));
}
__device__ __forceinline__ void mma8(float c[4], const unsigned a[4], unsigned b0, unsigned b1) {
    asm volatile(
        "mma.sync.aligned.m16n8k8.row.col.f32.tf32.tf32.f32 "
        "{%0,%1,%2,%3},{%4,%5,%6,%7},{%8,%9},{%0,%1,%2,%3};\n"
        : "+f"(c[0]), "+f"(c[1]), "+f"(c[2]), "+f"(c[3])
        : "r"(a[0]), "r"(a[1]), "r"(a[2]), "r"(a[3]), "r"(b0), "r"(b1));
}

// ---------------- tf32 tensor-core GEMM 128x128x16, double-buffered ----------------
__global__ void __launch_bounds__(256, 2)
tgemm_db(const float* __restrict__ A, const float* __restrict__ B,
         float* __restrict__ C,
         int M, int N, int K, int lda, int ldb, int ldc,
         long sA, long sB, long sC)
{
    __shared__ float As[2][16][132];   // [k][m], tf32 values
    __shared__ float Bs[2][16][132];   // [k][n], tf32 values

    const float* Ab = A + (long)blockIdx.z * sA;
    const float* Bb = B + (long)blockIdx.z * sB;
    float*       Cb = C + (long)blockIdx.z * sC;

    const int bm0 = blockIdx.y * 128;
    const int bn0 = blockIdx.x * 128;
    const int tid = threadIdx.x;
    const int w    = tid >> 5;
    const int lane = tid & 31;
    const int lq   = lane >> 2;
    const int lr   = lane & 3;
    const int wm0  = (w & 3) * 32;     // warp M base within tile
    const int wn0  = (w >> 2) * 64;    // warp N base within tile

    // loaders
    const int a_row = tid >> 1;
    const int a_k   = (tid & 1) * 8;
    const int b_k   = tid >> 5;
    const int b_col = (tid & 31) * 4;
    const bool bvalid = (bn0 + b_col) < N;

    float acc[2][8][4];
#pragma unroll
    for (int mi = 0; mi < 2; mi++)
#pragma unroll
        for (int ni = 0; ni < 8; ni++)
#pragma unroll
            for (int r = 0; r < 4; r++) acc[mi][ni][r] = 0.f;

    const int nc = K / 16;

    // prologue: chunk 0 -> buf 0
    {
        const float* ap = Ab + (long)(bm0 + a_row) * lda + a_k;
        float4 a0 = *(const float4*)(ap);
        float4 a1 = *(const float4*)(ap + 4);
        As[0][a_k + 0][a_row] = tf32f(a0.x); As[0][a_k + 1][a_row] = tf32f(a0.y);
        As[0][a_k + 2][a_row] = tf32f(a0.z); As[0][a_k + 3][a_row] = tf32f(a0.w);
        As[0][a_k + 4][a_row] = tf32f(a1.x); As[0][a_k + 5][a_row] = tf32f(a1.y);
        As[0][a_k + 6][a_row] = tf32f(a1.z); As[0][a_k + 7][a_row] = tf32f(a1.w);
        float4 z4 = make_float4(0.f, 0.f, 0.f, 0.f);
        float4 b0 = bvalid ? *(const float4*)(Bb + (long)b_k * ldb + bn0 + b_col) : z4;
        float4 b1 = bvalid ? *(const float4*)(Bb + (long)(b_k + 8) * ldb + bn0 + b_col) : z4;
        Bs[0][b_k][b_col + 0] = tf32f(b0.x); Bs[0][b_k][b_col + 1] = tf32f(b0.y);
        Bs[0][b_k][b_col + 2] = tf32f(b0.z); Bs[0][b_k][b_col + 3] = tf32f(b0.w);
        Bs[0][b_k + 8][b_col + 0] = tf32f(b1.x); Bs[0][b_k + 8][b_col + 1] = tf32f(b1.y);
        Bs[0][b_k + 8][b_col + 2] = tf32f(b1.z); Bs[0][b_k + 8][b_col + 3] = tf32f(b1.w);
    }
    __syncthreads();

    int buf = 0;
    for (int c = 0; c < nc; c++) {
        float4 a0, a1, b0, b1;
        const bool more = (c + 1 < nc);
        if (more) {
            const int k0 = (c + 1) * 16;
            const float* ap = Ab + (long)(bm0 + a_row) * lda + k0 + a_k;
            a0 = *(const float4*)(ap);
            a1 = *(const float4*)(ap + 4);
            float4 z4 = make_float4(0.f, 0.f, 0.f, 0.f);
            b0 = bvalid ? *(const float4*)(Bb + (long)(k0 + b_k) * ldb + bn0 + b_col) : z4;
            b1 = bvalid ? *(const float4*)(Bb + (long)(k0 + b_k + 8) * ldb + bn0 + b_col) : z4;
        }

        // compute on buf: 2 k-steps of 8
#pragma unroll
        for (int ks = 0; ks < 2; ks++) {
            const int kb = ks * 8;
            unsigned afr[2][4];
#pragma unroll
            for (int mi = 0; mi < 2; mi++) {
                const unsigned* r0 = (const unsigned*)&As[buf][kb + lr][wm0 + mi * 16 + lq];
                const unsigned* r1 = (const unsigned*)&As[buf][kb + lr + 4][wm0 + mi * 16 + lq];
                afr[mi][0] = r0[0]; afr[mi][1] = r0[8];
                afr[mi][2] = r1[0]; afr[mi][3] = r1[8];
            }
#pragma unroll
            for (int ni = 0; ni < 8; ni++) {
                unsigned bb0 = ((const unsigned*)&Bs[buf][kb + lr][wn0 + ni * 8 + lq])[0];
                unsigned bb1 = ((const unsigned*)&Bs[buf][kb + lr + 4][wn0 + ni * 8 + lq])[0];
                mma8(acc[0][ni], afr[0], bb0, bb1);
                mma8(acc[1][ni], afr[1], bb0, bb1);
            }
        }

        if (more) {
            const int nb = buf ^ 1;
            As[nb][a_k + 0][a_row] = tf32f(a0.x); As[nb][a_k + 1][a_row] = tf32f(a0.y);
            As[nb][a_k + 2][a_row] = tf32f(a0.z); As[nb][a_k + 3][a_row] = tf32f(a0.w);
            As[nb][a_k + 4][a_row] = tf32f(a1.x); As[nb][a_k + 5][a_row] = tf32f(a1.y);
            As[nb][a_k + 6][a_row] = tf32f(a1.z); As[nb][a_k + 7][a_row] = tf32f(a1.w);
            Bs[nb][b_k][b_col + 0] = tf32f(b0.x); Bs[nb][b_k][b_col + 1] = tf32f(b0.y);
            Bs[nb][b_k][b_col + 2] = tf32f(b0.z); Bs[nb][b_k][b_col + 3] = tf32f(b0.w);
            Bs[nb][b_k + 8][b_col + 0] = tf32f(b1.x); Bs[nb][b_k + 8][b_col + 1] = tf32f(b1.y);
            Bs[nb][b_k + 8][b_col + 2] = tf32f(b1.z); Bs[nb][b_k + 8][b_col + 3] = tf32f(b1.w);
        }
        __syncthreads();
        buf ^= 1;
    }

    // epilogue
#pragma unroll
    for (int mi = 0; mi < 2; mi++) {
        const int row0 = bm0 + wm0 + mi * 16 + lq;
#pragma unroll
        for (int ni = 0; ni < 8; ni++) {
            const int col = bn0 + wn0 + ni * 8 + 2 * lr;
            if (col < N) {
                *(float2*)(Cb + (long)row0 * ldc + col)       = make_float2(acc[mi][ni][0], acc[mi][ni][1]);
                *(float2*)(Cb + (long)(row0 + 8) * ldc + col) = make_float2(acc[mi][ni][2], acc[mi][ni][3]);
            }
        }
    }
}

// ---------------- RMSNorm over 768 ----------------
__global__ void rms768_kernel(const float* __restrict__ in, const float* __restrict__ g,
                              float* __restrict__ out)
{
    int t = blockIdx.x;
    const float* x = in + (long)t * QLORA_;
    int tid = threadIdx.x;
    __shared__ float red[256];
    float s = 0.f;
    for (int i = tid; i < QLORA_; i += 256) { float v = x[i]; s += v * v; }
    red[tid] = s;
    __syncthreads();
    for (int st = 128; st > 0; st >>= 1) { if (tid < st) red[tid] += red[tid + st]; __syncthreads(); }
    __shared__ float rinv;
    if (tid == 0) rinv = rsqrtf(red[0] / (float)QLORA_ + EPS_);
    __syncthreads();
    for (int i = tid; i < QLORA_; i += 256)
        out[(long)t * QLORA_ + i] = x[i] * rinv * g[i];
}

// ---------------- latent -> k_in ----------------
__global__ void latent_kernel(const float* __restrict__ lat, const float* __restrict__ g,
                              const int* __restrict__ pos, float* __restrict__ kin)
{
    int t = blockIdx.x;
    const float* x = lat + (long)t * DQK;
    int tid = threadIdx.x;
    __shared__ float red[256];
    float v = x[tid];
    red[tid] = v * v;
    __syncthreads();
    for (int st = 128; st > 0; st >>= 1) { if (tid < st) red[tid] += red[tid + st]; __syncthreads(); }
    __shared__ float rinv;
    if (tid == 0) rinv = rsqrtf(red[0] / (float)KVLORA_ + EPS_);
    __syncthreads();
    kin[(long)t * DQK + tid] = v * rinv * g[tid];
    if (tid < 16) {
        float p = (float)pos[t];
        float f = p * powf(10000.f, -(float)tid / 16.f);
        float c = cosf(f), s = sinf(f);
        float x1 = x[KVLORA_ + tid];
        float x2 = x[KVLORA_ + 16 + tid];
        kin[(long)t * DQK + KVLORA_ + tid]      = x1 * c - x2 * s;
        kin[(long)t * DQK + KVLORA_ + 16 + tid] = x2 * c + x1 * s;
    }
}

// ---------------- RoPE q_pe ----------------
__global__ void rope_q_kernel(const float* __restrict__ q, const int* __restrict__ pos,
                              float* __restrict__ qin)
{
    int idx = blockIdx.x * blockDim.x + threadIdx.x;
    if (idx >= T_ * H_ * 16) return;
    int j = idx & 15;
    int h = (idx >> 4) % H_;
    int t = idx / (16 * H_);
    float p = (float)pos[t];
    float f = p * powf(10000.f, -(float)j / 16.f);
    float c = cosf(f), s = sinf(f);
    const float* qp = q + (long)t * (H_ * QHD) + h * QHD + NOPE_;
    float x1 = qp[j], x2 = qp[16 + j];
    float* o = qin + (long)t * (H_ * DQK) + h * DQK + KVLORA_;
    o[j]      = x1 * c - x2 * s;
    o[16 + j] = x2 * c + x1 * s;
}

// ---------------- flash attention v3: tf32 mma.sync ----------------
#define QLD 292
#define KLD 36
#define VLD 264
#define PLD 68
#define ATTN_SMEM ((64*QLD + 2*64*KLD + 64*VLD + 64*PLD + 512 + 128) * 4)

__global__ void __launch_bounds__(256, 1)
attn3_kernel(const float* __restrict__ qin, const float* __restrict__ kin,
             float* __restrict__ olat)
{
    extern __shared__ float sm[];
    float* Qs     = sm;                      // [64][QLD] tf32
    float* Ks     = Qs + 64 * QLD;           // [2][64][KLD] tf32
    float* Vs     = Ks + 2 * 64 * KLD;       // [64][VLD] tf32
    float* Ps     = Vs + 64 * VLD;           // [64][PLD] tf32
    float* redmax = Ps + 64 * PLD;           // [64][4]
    float* redsum = redmax + 256;            // [64][4]
    float* m_s    = redsum + 256;            // [64]
    float* l_s    = m_s + 64;                // [64]

    const int h   = blockIdx.y;
    const int qb  = gridDim.x - 1 - blockIdx.x;   // heavy first
    const int i0  = qb * 64;
    const int tid = threadIdx.x;
    const int w    = tid >> 5;
    const int lane = tid & 31;
    const int wm   = (w & 1) * 32;
    const int wni  = w >> 1;
    const int wn   = wni * 16;
    const int wv   = wni * 64;
    const int lq   = lane >> 2;
    const int lr   = lane & 3;
    const float scale = 0.102062072615966f;  // 1/sqrt(96)

    {
        const int row = tid >> 2;
        const int cg  = (tid & 3) * 72;
        const float* src = qin + (size_t)(i0 + row) * (H_ * DQK) + h * DQK + cg;
        unsigned* dst = (unsigned*)(Qs + row * QLD + cg);
#pragma unroll
        for (int i = 0; i < 18; i++) {
            float4 v = *(const float4*)(src + i * 4);
            uint4 u;
            u.x = tf32c(v.x * scale); u.y = tf32c(v.y * scale);
            u.z = tf32c(v.z * scale); u.w = tf32c(v.w * scale);
            *(uint4*)(dst + i * 4) = u;
        }
    }
    if (tid < 64) { m_s[tid] = -1e30f; l_s[tid] = 0.f; }

    float o[2][8][4];
#pragma unroll
    for (int mi = 0; mi < 2; mi++)
#pragma unroll
        for (int ni = 0; ni < 8; ni++)
#pragma unroll
            for (int r = 0; r < 4; r++) o[mi][ni][r] = 0.f;

    const int krow = tid >> 2, kcg = (tid & 3) * 8;
    const int vrow = tid >> 2, vcg = (tid & 3) * 64;
    const int nkb = qb + 1;

    for (int kb = 0; kb < nkb; kb++) {
        const int j0 = kb * 64;
        __syncthreads();

        {
            const float* vsrc = kin + (size_t)(j0 + vrow) * DQK + vcg;
            unsigned* vdst = (unsigned*)(Vs + vrow * VLD + vcg);
#pragma unroll
            for (int i = 0; i < 16; i++) {
                float4 v = *(const float4*)(vsrc + i * 4);
                uint4 u;
                u.x = tf32c(v.x); u.y = tf32c(v.y); u.z = tf32c(v.z); u.w = tf32c(v.w);
                *(uint4*)(vdst + i * 4) = u;
            }
            const float* ksrc = kin + (size_t)(j0 + krow) * DQK + kcg;
            float4 t0 = *(const float4*)(ksrc);
            float4 t1 = *(const float4*)(ksrc + 4);
            uint4 u0, u1;
            u0.x = tf32c(t0.x); u0.y = tf32c(t0.y); u0.z = tf32c(t0.z); u0.w = tf32c(t0.w);
            u1.x = tf32c(t1.x); u1.y = tf32c(t1.y); u1.z = tf32c(t1.z); u1.w = tf32c(t1.w);
            unsigned* kdst = (unsigned*)(Ks + krow * KLD + kcg);
            *(uint4*)(kdst)     = u0;
            *(uint4*)(kdst + 4) = u1;
        }
        __syncthreads();

        float s[2][2][4];
#pragma unroll
        for (int mi = 0; mi < 2; mi++)
#pragma unroll
            for (int ni = 0; ni < 2; ni++)
#pragma unroll
                for (int r = 0; r < 4; r++) s[mi][ni][r] = 0.f;

        for (int c = 0; c < 9; c++) {
            uint4 pf0, pf1;
            if (c < 8) {
                const float* ksrc = kin + (size_t)(j0 + krow) * DQK + (c + 1) * 32 + kcg;
                float4 t0 = *(const float4*)(ksrc);
                float4 t1 = *(const float4*)(ksrc + 4);
                pf0.x = tf32c(t0.x); pf0.y = tf32c(t0.y); pf0.z = tf32c(t0.z); pf0.w = tf32c(t0.w);
                pf1.x = tf32c(t1.x); pf1.y = tf32c(t1.y); pf1.z = tf32c(t1.z); pf1.w = tf32c(t1.w);
            }
            const float* kbuf = Ks + (c & 1) * 64 * KLD;
            const int cb = c * 32;
#pragma unroll
            for (int ks = 0; ks < 4; ks++) {
                const int d0 = ks * 8;
                unsigned a[2][4];
#pragma unroll
                for (int mi = 0; mi < 2; mi++) {
                    const unsigned* q0 = (const unsigned*)(Qs + (wm + 16 * mi + lq) * QLD) + cb + d0 + lr;
                    const unsigned* q1 = q0 + 8 * QLD;
                    a[mi][0] = q0[0]; a[mi][1] = q1[0]; a[mi][2] = q0[4]; a[mi][3] = q1[4];
                }
#pragma unroll
                for (int ni = 0; ni < 2; ni++) {
                    const unsigned* kp = (const unsigned*)(kbuf + (wn + 8 * ni + lq) * KLD) + d0 + lr;
                    unsigned b0 = kp[0], b1 = kp[4];
                    mma8(s[0][ni], a[0], b0, b1);
                    mma8(s[1][ni], a[1], b0, b1);
                }
            }
            if (c < 8) {
                unsigned* kdst = (unsigned*)(Ks + ((c + 1) & 1) * 64 * KLD + krow * KLD + kcg);
                *(uint4*)(kdst)     = pf0;
                *(uint4*)(kdst + 4) = pf1;
            }
            __syncthreads();
        }

        if (kb == qb) {
#pragma unroll
            for (int mi = 0; mi < 2; mi++)
#pragma unroll
                for (int ni = 0; ni < 2; ni++)
#pragma unroll
                    for (int r = 0; r < 4; r++) {
                        int row = wm + 16 * mi + 8 * (r >> 1) + lq;
                        int col = wn + 8 * ni + 2 * lr + (r & 1);
                        if (col > row) s[mi][ni][r] = -1e30f;
                    }
        }

#pragma unroll
        for (int mi = 0; mi < 2; mi++)
#pragma unroll
            for (int half = 0; half < 2; half++) {
                float mx = fmaxf(fmaxf(s[mi][0][2*half], s[mi][0][2*half+1]),
                                 fmaxf(s[mi][1][2*half], s[mi][1][2*half+1]));
                mx = fmaxf(mx, __shfl_xor_sync(0xffffffffu, mx, 1));
                mx = fmaxf(mx, __shfl_xor_sync(0xffffffffu, mx, 2));
                if (lr == 0) redmax[(wm + 16 * mi + 8 * half + lq) * 4 + wni] = mx;
            }
        __syncthreads();

        float alpha[2][2], mnew[2][2];
#pragma unroll
        for (int mi = 0; mi < 2; mi++)
#pragma unroll
            for (int half = 0; half < 2; half++) {
                const int row = wm + 16 * mi + 8 * half + lq;
                const float* rp = redmax + row * 4;
                float bm = fmaxf(fmaxf(rp[0], rp[1]), fmaxf(rp[2], rp[3]));
                float mo = m_s[row];
                float mn = fmaxf(mo, bm);
                mnew[mi][half]  = mn;
                alpha[mi][half] = __expf(mo - mn);
                float p0[2], p1[2];
#pragma unroll
                for (int ni = 0; ni < 2; ni++) {
                    p0[ni] = __expf(s[mi][ni][2*half]     - mn);
                    p1[ni] = __expf(s[mi][ni][2*half + 1] - mn);
                }
                float su = p0[0] + p1[0] + p0[1] + p1[1];
                su += __shfl_xor_sync(0xffffffffu, su, 1);
                su += __shfl_xor_sync(0xffffffffu, su, 2);
                if (lr == 0) redsum[row * 4 + wni] = su;
#pragma unroll
                for (int ni = 0; ni < 2; ni++) {
                    unsigned* pp = (unsigned*)(Ps + row * PLD + wn + 8 * ni + 2 * lr);
                    pp[0] = tf32c(p0[ni]);
                    pp[1] = tf32c(p1[ni]);
                }
            }
#pragma unroll
        for (int mi = 0; mi < 2; mi++)
#pragma unroll
            for (int ni = 0; ni < 8; ni++) {
                o[mi][ni][0] *= alpha[mi][0];
                o[mi][ni][1] *= alpha[mi][0];
                o[mi][ni][2] *= alpha[mi][1];
                o[mi][ni][3] *= alpha[mi][1];
            }
        __syncthreads();

        if (w < 2 && lr == 0) {
#pragma unroll
            for (int mi = 0; mi < 2; mi++)
#pragma unroll
                for (int half = 0; half < 2; half++) {
                    const int row = wm + 16 * mi + 8 * half + lq;
                    const float* rp = redsum + row * 4;
                    l_s[row] = l_s[row] * alpha[mi][half] + (rp[0] + rp[1] + rp[2] + rp[3]);
                    m_s[row] = mnew[mi][half];
                }
        }

#pragma unroll
        for (int kst = 0; kst < 8; kst++) {
            unsigned a[2][4];
#pragma unroll
            for (int mi = 0; mi < 2; mi++) {
                const unsigned* p0 = (const unsigned*)(Ps + (wm + 16 * mi + lq) * PLD) + kst * 8 + lr;
                const unsigned* p1 = p0 + 8 * PLD;
                a[mi][0] = p0[0]; a[mi][1] = p1[0]; a[mi][2] = p0[4]; a[mi][3] = p1[4];
            }
            const unsigned* vrow0 = (const unsigned*)(Vs + (kst * 8 + lr) * VLD);
#pragma unroll
            for (int ni = 0; ni < 8; ni++) {
                unsigned b0 = vrow0[wv + 8 * ni + lq];
                unsigned b1 = vrow0[4 * VLD + wv + 8 * ni + lq];
                mma8(o[0][ni], a[0], b0, b1);
                mma8(o[1][ni], a[1], b0, b1);
            }
        }
    }

    __syncthreads();
#pragma unroll
    for (int mi = 0; mi < 2; mi++)
#pragma unroll
        for (int half = 0; half < 2; half++) {
            const int row = wm + 16 * mi + 8 * half + lq;
            const float linv = 1.f / l_s[row];
            float* dst = olat + (size_t)(i0 + row) * (H_ * KVLORA_) + h * KVLORA_;
#pragma unroll
            for (int ni = 0; ni < 8; ni++) {
                float2 v = make_float2(o[mi][ni][2*half] * linv, o[mi][ni][2*half + 1] * linv);
                *(float2*)(dst + wv + 8 * ni + 2 * lr) = v;
            }
        }
}

// ---------------- host ----------------
extern "C" void kernel_launch(void* const* d_in, const int* in_sizes, int n_in,
                              void* d_out, int out_size)
{
    const int*   positions = (const int*)  d_in[0];
    const float* hidden    = (const float*)d_in[1];
    const float* w_qa      = (const float*)d_in[2];
    const float* g_qa      = (const float*)d_in[3];
    const float* w_qb      = (const float*)d_in[4];
    const float* w_kva     = (const float*)d_in[5];
    const float* g_kva     = (const float*)d_in[6];
    const float* w_kc      = (const float*)d_in[7];
    const float* w_vc      = (const float*)d_in[8];
    const float* w_o       = (const float*)d_in[9];
    float* out = (float*)d_out;

    float *qa, *qan, *q, *lat, *kin, *qin, *olat, *ov;
    cudaGetSymbolAddress((void**)&qa,   sc_qa);
    cudaGetSymbolAddress((void**)&qan,  sc_qan);
    cudaGetSymbolAddress((void**)&q,    sc_q);
    cudaGetSymbolAddress((void**)&lat,  sc_lat);
    cudaGetSymbolAddress((void**)&kin,  sc_kin);
    cudaGetSymbolAddress((void**)&qin,  sc_qin);
    cudaGetSymbolAddress((void**)&olat, sc_olat);
    cudaGetSymbolAddress((void**)&ov,   sc_ov);

    cudaFuncSetAttribute(attn3_kernel, cudaFuncAttributeMaxDynamicSharedMemorySize, ATTN_SMEM);

    dim3 thr(256);

    // 1) qa = hidden @ w_qa
    tgemm_db<<<dim3(QLORA_/128, T_/128, 1), thr>>>(hidden, w_qa, qa,
        T_, QLORA_, HID_, HID_, QLORA_, QLORA_, 0, 0, 0);
    // 2) rmsnorm
    rms768_kernel<<<T_, thr>>>(qa, g_qa, qan);
    // 3) q = qan @ w_qb
    tgemm_db<<<dim3((H_*QHD)/128, T_/128, 1), thr>>>(qan, w_qb, q,
        T_, H_*QHD, QLORA_, QLORA_, H_*QHD, H_*QHD, 0, 0, 0);
    // 4) latent = hidden @ w_kva
    tgemm_db<<<dim3((DQK+127)/128, T_/128, 1), thr>>>(hidden, w_kva, lat,
        T_, DQK, HID_, HID_, DQK, DQK, 0, 0, 0);
    // 5) k_in build
    latent_kernel<<<T_, thr>>>(lat, g_kva, positions, kin);
    // 6) q_lat batched over heads
    tgemm_db<<<dim3(KVLORA_/128, T_/128, H_), thr>>>(q, w_kc, qin,
        T_, KVLORA_, NOPE_, H_*QHD, KVLORA_, H_*DQK,
        (long)QHD, (long)NOPE_*KVLORA_, (long)DQK);
    // 7) rope q_pe
    rope_q_kernel<<<(T_*H_*16 + 255)/256, thr>>>(q, positions, qin);
    // 8) attention (tf32 mma)
    attn3_kernel<<<dim3(T_/64, H_), thr, ATTN_SMEM>>>(qin, kin, olat);
    // 9) v-proj batched
    tgemm_db<<<dim3(1, T_/128, H_), thr>>>(olat, w_vc, ov,
        T_, VDIM_, KVLORA_, H_*KVLORA_, VDIM_, H_*VDIM_,
        (long)KVLORA_, (long)KVLORA_*VDIM_, (long)VDIM_);
    // 10) out = ov @ w_o
    tgemm_db<<<dim3(HID_/128, T_/128, 1), thr>>>(ov, w_o, out,
        T_, HID_, H_*VDIM_, H_*VDIM_, HID_, HID_, 0, 0, 0);
}

// round 5
// speedup vs baseline: 7.7838x; 1.1153x over previous
#include <cuda_runtime.h>
#include <math.h>

#define T_      2048
#define HID_    2560
#define H_      40
#define NOPE_   64
#define ROPE_   32
#define VDIM_   64
#define QLORA_  768
#define KVLORA_ 256
#define DQK     288
#define QHD     96
#define EPS_    1e-5f

// ---------------- scratch ----------------
__device__ float sc_qa  [T_ * QLORA_];
__device__ float sc_qan [T_ * QLORA_];
__device__ float sc_q   [T_ * H_ * QHD];
__device__ float sc_lat [T_ * DQK];
__device__ float sc_kin [T_ * DQK];
__device__ float sc_qin [(size_t)T_ * H_ * DQK];
__device__ float sc_olat[(size_t)T_ * H_ * KVLORA_];
__device__ float sc_ov  [T_ * H_ * VDIM_];

// ---------------- tf32 / mma / cp.async helpers ----------------
__device__ __forceinline__ unsigned tf32c(float x) {
    unsigned u;
    asm("cvt.rna.tf32.f32 %0, %1;" : "=r"(u) : "f"(x));
    return u;
}
__device__ __forceinline__ void mma8(float c[4], const unsigned a[4], unsigned b0, unsigned b1) {
    asm volatile(
        "mma.sync.aligned.m16n8k8.row.col.f32.tf32.tf32.f32 "
        "{%0,%1,%2,%3},{%4,%5,%6,%7},{%8,%9},{%0,%1,%2,%3};\n"
        : "+f"(c[0]), "+f"(c[1]), "+f"(c[2]), "+f"(c[3])
        : "r"(a[0]), "r"(a[1]), "r"(a[2]), "r"(a[3]), "r"(b0), "r"(b1));
}
__device__ __forceinline__ void cp16(unsigned dst, const void* src, int sz) {
    asm volatile("cp.async.ca.shared.global [%0], [%1], 16, %2;\n"
                 :: "r"(dst), "l"(src), "r"(sz));
}
#define CP_COMMIT() asm volatile("cp.async.commit_group;\n" ::: "memory")
#define CP_WAIT(n)  asm volatile("cp.async.wait_group %0;\n" :: "n"(n) : "memory")

// ---------------- tf32 GEMM 128x128x16, cp.async 4-stage pipeline ----------------
#define NST 4
#define ALD 20     // A row stride (floats): banks (20*lq+lr)%32 all distinct
#define BLD 136    // B row stride (floats): banks (8*lr+lq)%32 all distinct
#define A_ST (128 * ALD)
#define B_ST (16 * BLD)
#define GEMM_SMEM ((NST * A_ST + NST * B_ST) * 4)

__global__ void __launch_bounds__(256, 2)
tgemm_ca(const float* __restrict__ A, const float* __restrict__ B,
         float* __restrict__ C,
         int M, int N, int K, int lda, int ldb, int ldc,
         long sA, long sB, long sC)
{
    extern __shared__ float smem[];
    float* Asm = smem;                 // [NST][128][ALD]  raw fp32, [m][k]
    float* Bsm = smem + NST * A_ST;    // [NST][16][BLD]   raw fp32, [k][n]

    const float* Ab = A + (long)blockIdx.z * sA;
    const float* Bb = B + (long)blockIdx.z * sB;
    float*       Cb = C + (long)blockIdx.z * sC;

    const int bm0 = blockIdx.y * 128;
    const int bn0 = blockIdx.x * 128;
    const int tid = threadIdx.x;
    const int w    = tid >> 5;
    const int lane = tid & 31;
    const int lq   = lane >> 2;
    const int lr   = lane & 3;
    const int wm0  = (w & 3) * 32;
    const int wn0  = (w >> 2) * 64;

    // loader indices
    const int a_row = tid >> 1;
    const int a_k0  = (tid & 1) * 8;            // chunks at a_k0, a_k0+4
    const int b_r0  = tid >> 5;                 // rows b_r0, b_r0+8
    const int b_c0  = (tid & 31) * 4;
    const int b_sz  = (bn0 + b_c0 < N) ? 16 : 0;

    const unsigned a_dst0 = (unsigned)__cvta_generic_to_shared(Asm) + (a_row * ALD + a_k0) * 4;
    const unsigned b_dst0 = (unsigned)__cvta_generic_to_shared(Bsm) + (b_r0 * BLD + b_c0) * 4;

    float acc[2][8][4];
#pragma unroll
    for (int mi = 0; mi < 2; mi++)
#pragma unroll
        for (int ni = 0; ni < 8; ni++)
#pragma unroll
            for (int r = 0; r < 4; r++) acc[mi][ni][r] = 0.f;

    const int nc = K / 16;

    // prologue: fill first NST-1 stages
#pragma unroll
    for (int s = 0; s < NST - 1; s++) {
        if (s < nc) {
            const int k0 = s * 16;
            const float* ap = Ab + (long)(bm0 + a_row) * lda + k0 + a_k0;
            cp16(a_dst0 + s * A_ST * 4,      ap,     16);
            cp16(a_dst0 + s * A_ST * 4 + 16, ap + 4, 16);
            const float* bp = Bb + (long)(k0 + b_r0) * ldb + bn0 + b_c0;
            cp16(b_dst0 + s * B_ST * 4,                 bp,           b_sz);
            cp16(b_dst0 + s * B_ST * 4 + 8 * BLD * 4,   bp + 8 * ldb, b_sz);
        }
        CP_COMMIT();
    }

    int buf = 0;
    for (int c = 0; c < nc; c++) {
        CP_WAIT(NST - 2);
        __syncthreads();

        const float* Ab_s = Asm + buf * A_ST;
        const float* Bb_s = Bsm + buf * B_ST;
#pragma unroll
        for (int ks = 0; ks < 2; ks++) {
            const int kb = ks * 8;
            unsigned afr[2][4];
#pragma unroll
            for (int mi = 0; mi < 2; mi++) {
                const float* r0 = Ab_s + (wm0 + 16 * mi + lq) * ALD + kb + lr;
                afr[mi][0] = tf32c(r0[0]);
                afr[mi][1] = tf32c(r0[8 * ALD]);
                afr[mi][2] = tf32c(r0[4]);
                afr[mi][3] = tf32c(r0[8 * ALD + 4]);
            }
            const float* brow0 = Bb_s + (kb + lr) * BLD + wn0 + lq;
            const float* brow1 = brow0 + 4 * BLD;
#pragma unroll
            for (int ni = 0; ni < 8; ni++) {
                unsigned b0 = tf32c(brow0[ni * 8]);
                unsigned b1 = tf32c(brow1[ni * 8]);
                mma8(acc[0][ni], afr[0], b0, b1);
                mma8(acc[1][ni], afr[1], b0, b1);
            }
        }

        // issue stage c + NST-1
        const int cs = c + NST - 1;
        if (cs < nc) {
            const int st = cs % NST;
            const int k0 = cs * 16;
            const float* ap = Ab + (long)(bm0 + a_row) * lda + k0 + a_k0;
            cp16(a_dst0 + st * A_ST * 4,      ap,     16);
            cp16(a_dst0 + st * A_ST * 4 + 16, ap + 4, 16);
            const float* bp = Bb + (long)(k0 + b_r0) * ldb + bn0 + b_c0;
            cp16(b_dst0 + st * B_ST * 4,               bp,           b_sz);
            cp16(b_dst0 + st * B_ST * 4 + 8 * BLD * 4, bp + 8 * ldb, b_sz);
        }
        CP_COMMIT();
        buf = (buf + 1 < NST) ? buf + 1 : 0;
    }

    // epilogue
#pragma unroll
    for (int mi = 0; mi < 2; mi++) {
        const int row0 = bm0 + wm0 + mi * 16 + lq;
#pragma unroll
        for (int ni = 0; ni < 8; ni++) {
            const int col = bn0 + wn0 + ni * 8 + 2 * lr;
            if (col < N) {
                *(float2*)(Cb + (long)row0 * ldc + col)       = make_float2(acc[mi][ni][0], acc[mi][ni][1]);
                *(float2*)(Cb + (long)(row0 + 8) * ldc + col) = make_float2(acc[mi][ni][2], acc[mi][ni][3]);
            }
        }
    }
}

// ---------------- RMSNorm over 768 ----------------
__global__ void rms768_kernel(const float* __restrict__ in, const float* __restrict__ g,
                              float* __restrict__ out)
{
    int t = blockIdx.x;
    const float* x = in + (long)t * QLORA_;
    int tid = threadIdx.x;
    __shared__ float red[256];
    float s = 0.f;
    for (int i = tid; i < QLORA_; i += 256) { float v = x[i]; s += v * v; }
    red[tid] = s;
    __syncthreads();
    for (int st = 128; st > 0; st >>= 1) { if (tid < st) red[tid] += red[tid + st]; __syncthreads(); }
    __shared__ float rinv;
    if (tid == 0) rinv = rsqrtf(red[0] / (float)QLORA_ + EPS_);
    __syncthreads();
    for (int i = tid; i < QLORA_; i += 256)
        out[(long)t * QLORA_ + i] = x[i] * rinv * g[i];
}

// ---------------- latent -> k_in ----------------
__global__ void latent_kernel(const float* __restrict__ lat, const float* __restrict__ g,
                              const int* __restrict__ pos, float* __restrict__ kin)
{
    int t = blockIdx.x;
    const float* x = lat + (long)t * DQK;
    int tid = threadIdx.x;
    __shared__ float red[256];
    float v = x[tid];
    red[tid] = v * v;
    __syncthreads();
    for (int st = 128; st > 0; st >>= 1) { if (tid < st) red[tid] += red[tid + st]; __syncthreads(); }
    __shared__ float rinv;
    if (tid == 0) rinv = rsqrtf(red[0] / (float)KVLORA_ + EPS_);
    __syncthreads();
    kin[(long)t * DQK + tid] = v * rinv * g[tid];
    if (tid < 16) {
        float p = (float)pos[t];
        float f = p * powf(10000.f, -(float)tid / 16.f);
        float c = cosf(f), s = sinf(f);
        float x1 = x[KVLORA_ + tid];
        float x2 = x[KVLORA_ + 16 + tid];
        kin[(long)t * DQK + KVLORA_ + tid]      = x1 * c - x2 * s;
        kin[(long)t * DQK + KVLORA_ + 16 + tid] = x2 * c + x1 * s;
    }
}

// ---------------- RoPE q_pe ----------------
__global__ void rope_q_kernel(const float* __restrict__ q, const int* __restrict__ pos,
                              float* __restrict__ qin)
{
    int idx = blockIdx.x * blockDim.x + threadIdx.x;
    if (idx >= T_ * H_ * 16) return;
    int j = idx & 15;
    int h = (idx >> 4) % H_;
    int t = idx / (16 * H_);
    float p = (float)pos[t];
    float f = p * powf(10000.f, -(float)j / 16.f);
    float c = cosf(f), s = sinf(f);
    const float* qp = q + (long)t * (H_ * QHD) + h * QHD + NOPE_;
    float x1 = qp[j], x2 = qp[16 + j];
    float* o = qin + (long)t * (H_ * DQK) + h * DQK + KVLORA_;
    o[j]      = x1 * c - x2 * s;
    o[16 + j] = x2 * c + x1 * s;
}

// ---------------- flash attention v3: tf32 mma.sync ----------------
#define QLD 292
#define KLD 36
#define VLD 264
#define PLD 68
#define ATTN_SMEM ((64*QLD + 2*64*KLD + 64*VLD + 64*PLD + 512 + 128) * 4)

__global__ void __launch_bounds__(256, 1)
attn3_kernel(const float* __restrict__ qin, const float* __restrict__ kin,
             float* __restrict__ olat)
{
    extern __shared__ float sm[];
    float* Qs     = sm;
    float* Ks     = Qs + 64 * QLD;
    float* Vs     = Ks + 2 * 64 * KLD;
    float* Ps     = Vs + 64 * VLD;
    float* redmax = Ps + 64 * PLD;
    float* redsum = redmax + 256;
    float* m_s    = redsum + 256;
    float* l_s    = m_s + 64;

    const int h   = blockIdx.y;
    const int qb  = gridDim.x - 1 - blockIdx.x;
    const int i0  = qb * 64;
    const int tid = threadIdx.x;
    const int w    = tid >> 5;
    const int lane = tid & 31;
    const int wm   = (w & 1) * 32;
    const int wni  = w >> 1;
    const int wn   = wni * 16;
    const int wv   = wni * 64;
    const int lq   = lane >> 2;
    const int lr   = lane & 3;
    const float scale = 0.102062072615966f;  // 1/sqrt(96)

    {
        const int row = tid >> 2;
        const int cg  = (tid & 3) * 72;
        const float* src = qin + (size_t)(i0 + row) * (H_ * DQK) + h * DQK + cg;
        unsigned* dst = (unsigned*)(Qs + row * QLD + cg);
#pragma unroll
        for (int i = 0; i < 18; i++) {
            float4 v = *(const float4*)(src + i * 4);
            uint4 u;
            u.x = tf32c(v.x * scale); u.y = tf32c(v.y * scale);
            u.z = tf32c(v.z * scale); u.w = tf32c(v.w * scale);
            *(uint4*)(dst + i * 4) = u;
        }
    }
    if (tid < 64) { m_s[tid] = -1e30f; l_s[tid] = 0.f; }

    float o[2][8][4];
#pragma unroll
    for (int mi = 0; mi < 2; mi++)
#pragma unroll
        for (int ni = 0; ni < 8; ni++)
#pragma unroll
            for (int r = 0; r < 4; r++) o[mi][ni][r] = 0.f;

    const int krow = tid >> 2, kcg = (tid & 3) * 8;
    const int vrow = tid >> 2, vcg = (tid & 3) * 64;
    const int nkb = qb + 1;

    for (int kb = 0; kb < nkb; kb++) {
        const int j0 = kb * 64;
        __syncthreads();

        {
            const float* vsrc = kin + (size_t)(j0 + vrow) * DQK + vcg;
            unsigned* vdst = (unsigned*)(Vs + vrow * VLD + vcg);
#pragma unroll
            for (int i = 0; i < 16; i++) {
                float4 v = *(const float4*)(vsrc + i * 4);
                uint4 u;
                u.x = tf32c(v.x); u.y = tf32c(v.y); u.z = tf32c(v.z); u.w = tf32c(v.w);
                *(uint4*)(vdst + i * 4) = u;
            }
            const float* ksrc = kin + (size_t)(j0 + krow) * DQK + kcg;
            float4 t0 = *(const float4*)(ksrc);
            float4 t1 = *(const float4*)(ksrc + 4);
            uint4 u0, u1;
            u0.x = tf32c(t0.x); u0.y = tf32c(t0.y); u0.z = tf32c(t0.z); u0.w = tf32c(t0.w);
            u1.x = tf32c(t1.x); u1.y = tf32c(t1.y); u1.z = tf32c(t1.z); u1.w = tf32c(t1.w);
            unsigned* kdst = (unsigned*)(Ks + krow * KLD + kcg);
            *(uint4*)(kdst)     = u0;
            *(uint4*)(kdst + 4) = u1;
        }
        __syncthreads();

        float s[2][2][4];
#pragma unroll
        for (int mi = 0; mi < 2; mi++)
#pragma unroll
            for (int ni = 0; ni < 2; ni++)
#pragma unroll
                for (int r = 0; r < 4; r++) s[mi][ni][r] = 0.f;

        for (int c = 0; c < 9; c++) {
            uint4 pf0, pf1;
            if (c < 8) {
                const float* ksrc = kin + (size_t)(j0 + krow) * DQK + (c + 1) * 32 + kcg;
                float4 t0 = *(const float4*)(ksrc);
                float4 t1 = *(const float4*)(ksrc + 4);
                pf0.x = tf32c(t0.x); pf0.y = tf32c(t0.y); pf0.z = tf32c(t0.z); pf0.w = tf32c(t0.w);
                pf1.x = tf32c(t1.x); pf1.y = tf32c(t1.y); pf1.z = tf32c(t1.z); pf1.w = tf32c(t1.w);
            }
            const float* kbuf = Ks + (c & 1) * 64 * KLD;
            const int cb = c * 32;
#pragma unroll
            for (int ks = 0; ks < 4; ks++) {
                const int d0 = ks * 8;
                unsigned a[2][4];
#pragma unroll
                for (int mi = 0; mi < 2; mi++) {
                    const unsigned* q0 = (const unsigned*)(Qs + (wm + 16 * mi + lq) * QLD) + cb + d0 + lr;
                    const unsigned* q1 = q0 + 8 * QLD;
                    a[mi][0] = q0[0]; a[mi][1] = q1[0]; a[mi][2] = q0[4]; a[mi][3] = q1[4];
                }
#pragma unroll
                for (int ni = 0; ni < 2; ni++) {
                    const unsigned* kp = (const unsigned*)(kbuf + (wn + 8 * ni + lq) * KLD) + d0 + lr;
                    unsigned b0 = kp[0], b1 = kp[4];
                    mma8(s[0][ni], a[0], b0, b1);
                    mma8(s[1][ni], a[1], b0, b1);
                }
            }
            if (c < 8) {
                unsigned* kdst = (unsigned*)(Ks + ((c + 1) & 1) * 64 * KLD + krow * KLD + kcg);
                *(uint4*)(kdst)     = pf0;
                *(uint4*)(kdst + 4) = pf1;
            }
            __syncthreads();
        }

        if (kb == qb) {
#pragma unroll
            for (int mi = 0; mi < 2; mi++)
#pragma unroll
                for (int ni = 0; ni < 2; ni++)
#pragma unroll
                    for (int r = 0; r < 4; r++) {
                        int row = wm + 16 * mi + 8 * (r >> 1) + lq;
                        int col = wn + 8 * ni + 2 * lr + (r & 1);
                        if (col > row) s[mi][ni][r] = -1e30f;
                    }
        }

#pragma unroll
        for (int mi = 0; mi < 2; mi++)
#pragma unroll
            for (int half = 0; half < 2; half++) {
                float mx = fmaxf(fmaxf(s[mi][0][2*half], s[mi][0][2*half+1]),
                                 fmaxf(s[mi][1][2*half], s[mi][1][2*half+1]));
                mx = fmaxf(mx, __shfl_xor_sync(0xffffffffu, mx, 1));
                mx = fmaxf(mx, __shfl_xor_sync(0xffffffffu, mx, 2));
                if (lr == 0) redmax[(wm + 16 * mi + 8 * half + lq) * 4 + wni] = mx;
            }
        __syncthreads();

        float alpha[2][2], mnew[2][2];
#pragma unroll
        for (int mi = 0; mi < 2; mi++)
#pragma unroll
            for (int half = 0; half < 2; half++) {
                const int row = wm + 16 * mi + 8 * half + lq;
                const float* rp = redmax + row * 4;
                float bm = fmaxf(fmaxf(rp[0], rp[1]), fmaxf(rp[2], rp[3]));
                float mo = m_s[row];
                float mn = fmaxf(mo, bm);
                mnew[mi][half]  = mn;
                alpha[mi][half] = __expf(mo - mn);
                float p0[2], p1[2];
#pragma unroll
                for (int ni = 0; ni < 2; ni++) {
                    p0[ni] = __expf(s[mi][ni][2*half]     - mn);
                    p1[ni] = __expf(s[mi][ni][2*half + 1] - mn);
                }
                float su = p0[0] + p1[0] + p0[1] + p1[1];
                su += __shfl_xor_sync(0xffffffffu, su, 1);
                su += __shfl_xor_sync(0xffffffffu, su, 2);
                if (lr == 0) redsum[row * 4 + wni] = su;
#pragma unroll
                for (int ni = 0; ni < 2; ni++) {
                    unsigned* pp = (unsigned*)(Ps + row * PLD + wn + 8 * ni + 2 * lr);
                    pp[0] = tf32c(p0[ni]);
                    pp[1] = tf32c(p1[ni]);
                }
            }
#pragma unroll
        for (int mi = 0; mi < 2; mi++)
#pragma unroll
            for (int ni = 0; ni < 8; ni++) {
                o[mi][ni][0] *= alpha[mi][0];
                o[mi][ni][1] *= alpha[mi][0];
                o[mi][ni][2] *= alpha[mi][1];
                o[mi][ni][3] *= alpha[mi][1];
            }
        __syncthreads();

        if (w < 2 && lr == 0) {
#pragma unroll
            for (int mi = 0; mi < 2; mi++)
#pragma unroll
                for (int half = 0; half < 2; half++) {
                    const int row = wm + 16 * mi + 8 * half + lq;
                    const float* rp = redsum + row * 4;
                    l_s[row] = l_s[row] * alpha[mi][half] + (rp[0] + rp[1] + rp[2] + rp[3]);
                    m_s[row] = mnew[mi][half];
                }
        }

#pragma unroll
        for (int kst = 0; kst < 8; kst++) {
            unsigned a[2][4];
#pragma unroll
            for (int mi = 0; mi < 2; mi++) {
                const unsigned* p0 = (const unsigned*)(Ps + (wm + 16 * mi + lq) * PLD) + kst * 8 + lr;
                const unsigned* p1 = p0 + 8 * PLD;
                a[mi][0] = p0[0]; a[mi][1] = p1[0]; a[mi][2] = p0[4]; a[mi][3] = p1[4];
            }
            const unsigned* vrow0 = (const unsigned*)(Vs + (kst * 8 + lr) * VLD);
#pragma unroll
            for (int ni = 0; ni < 8; ni++) {
                unsigned b0 = vrow0[wv + 8 * ni + lq];
                unsigned b1 = vrow0[4 * VLD + wv + 8 * ni + lq];
                mma8(o[0][ni], a[0], b0, b1);
                mma8(o[1][ni], a[1], b0, b1);
            }
        }
    }

    __syncthreads();
#pragma unroll
    for (int mi = 0; mi < 2; mi++)
#pragma unroll
        for (int half = 0; half < 2; half++) {
            const int row = wm + 16 * mi + 8 * half + lq;
            const float linv = 1.f / l_s[row];
            float* dst = olat + (size_t)(i0 + row) * (H_ * KVLORA_) + h * KVLORA_;
#pragma unroll
            for (int ni = 0; ni < 8; ni++) {
                float2 v = make_float2(o[mi][ni][2*half] * linv, o[mi][ni][2*half + 1] * linv);
                *(float2*)(dst + wv + 8 * ni + 2 * lr) = v;
            }
        }
}

// ---------------- host ----------------
extern "C" void kernel_launch(void* const* d_in, const int* in_sizes, int n_in,
                              void* d_out, int out_size)
{
    const int*   positions = (const int*)  d_in[0];
    const float* hidden    = (const float*)d_in[1];
    const float* w_qa      = (const float*)d_in[2];
    const float* g_qa      = (const float*)d_in[3];
    const float* w_qb      = (const float*)d_in[4];
    const float* w_kva     = (const float*)d_in[5];
    const float* g_kva     = (const float*)d_in[6];
    const float* w_kc      = (const float*)d_in[7];
    const float* w_vc      = (const float*)d_in[8];
    const float* w_o       = (const float*)d_in[9];
    float* out = (float*)d_out;

    float *qa, *qan, *q, *lat, *kin, *qin, *olat, *ov;
    cudaGetSymbolAddress((void**)&qa,   sc_qa);
    cudaGetSymbolAddress((void**)&qan,  sc_qan);
    cudaGetSymbolAddress((void**)&q,    sc_q);
    cudaGetSymbolAddress((void**)&lat,  sc_lat);
    cudaGetSymbolAddress((void**)&kin,  sc_kin);
    cudaGetSymbolAddress((void**)&qin,  sc_qin);
    cudaGetSymbolAddress((void**)&olat, sc_olat);
    cudaGetSymbolAddress((void**)&ov,   sc_ov);

    cudaFuncSetAttribute(attn3_kernel, cudaFuncAttributeMaxDynamicSharedMemorySize, ATTN_SMEM);
    cudaFuncSetAttribute(tgemm_ca,     cudaFuncAttributeMaxDynamicSharedMemorySize, GEMM_SMEM);

    dim3 thr(256);

    // 1) qa = hidden @ w_qa
    tgemm_ca<<<dim3(QLORA_/128, T_/128, 1), thr, GEMM_SMEM>>>(hidden, w_qa, qa,
        T_, QLORA_, HID_, HID_, QLORA_, QLORA_, 0, 0, 0);
    // 2) rmsnorm
    rms768_kernel<<<T_, thr>>>(qa, g_qa, qan);
    // 3) q = qan @ w_qb
    tgemm_ca<<<dim3((H_*QHD)/128, T_/128, 1), thr, GEMM_SMEM>>>(qan, w_qb, q,
        T_, H_*QHD, QLORA_, QLORA_, H_*QHD, H_*QHD, 0, 0, 0);
    // 4) latent = hidden @ w_kva
    tgemm_ca<<<dim3((DQK+127)/128, T_/128, 1), thr, GEMM_SMEM>>>(hidden, w_kva, lat,
        T_, DQK, HID_, HID_, DQK, DQK, 0, 0, 0);
    // 5) k_in build
    latent_kernel<<<T_, thr>>>(lat, g_kva, positions, kin);
    // 6) q_lat batched over heads
    tgemm_ca<<<dim3(KVLORA_/128, T_/128, H_), thr, GEMM_SMEM>>>(q, w_kc, qin,
        T_, KVLORA_, NOPE_, H_*QHD, KVLORA_, H_*DQK,
        (long)QHD, (long)NOPE_*KVLORA_, (long)DQK);
    // 7) rope q_pe
    rope_q_kernel<<<(T_*H_*16 + 255)/256, thr>>>(q, positions, qin);
    // 8) attention (tf32 mma)
    attn3_kernel<<<dim3(T_/64, H_), thr, ATTN_SMEM>>>(qin, kin, olat);
    // 9) v-proj batched
    tgemm_ca<<<dim3(1, T_/128, H_), thr, GEMM_SMEM>>>(olat, w_vc, ov,
        T_, VDIM_, KVLORA_, H_*KVLORA_, VDIM_, H_*VDIM_,
        (long)KVLORA_, (long)KVLORA_*VDIM_, (long)VDIM_);
    // 10) out = ov @ w_o
    tgemm_ca<<<dim3(HID_/128, T_/128, 1), thr, GEMM_SMEM>>>(ov, w_o, out,
        T_, HID_, H_*VDIM_, H_*VDIM_, HID_, HID_, 0, 0, 0);
}

// round 6
// speedup vs baseline: 10.0992x; 1.2975x over previous
#include <cuda_runtime.h>
#include <math.h>

#define T_      2048
#define HID_    2560
#define H_      40
#define NOPE_   64
#define ROPE_   32
#define VDIM_   64
#define QLORA_  768
#define KVLORA_ 256
#define DQK     288
#define QHD     96
#define EPS_    1e-5f

// ---------------- scratch ----------------
__device__ float sc_qa  [T_ * QLORA_];
__device__ float sc_qan [T_ * QLORA_];
__device__ float sc_q   [T_ * H_ * QHD];
__device__ float sc_lat [T_ * DQK];
__device__ float sc_kin [T_ * DQK];
__device__ float sc_qin [(size_t)T_ * H_ * DQK];
__device__ float sc_olat[(size_t)T_ * H_ * KVLORA_];
__device__ float sc_ov  [T_ * H_ * VDIM_];

// ---------------- tf32 / mma / cp.async helpers ----------------
__device__ __forceinline__ unsigned tf32c(float x) {
    unsigned u;
    asm("cvt.rna.tf32.f32 %0, %1;" : "=r"(u) : "f"(x));
    return u;
}
__device__ __forceinline__ void mma8(float c[4], const unsigned a[4], unsigned b0, unsigned b1) {
    asm volatile(
        "mma.sync.aligned.m16n8k8.row.col.f32.tf32.tf32.f32 "
        "{%0,%1,%2,%3},{%4,%5,%6,%7},{%8,%9},{%0,%1,%2,%3};\n"
        : "+f"(c[0]), "+f"(c[1]), "+f"(c[2]), "+f"(c[3])
        : "r"(a[0]), "r"(a[1]), "r"(a[2]), "r"(a[3]), "r"(b0), "r"(b1));
}
__device__ __forceinline__ void cp16(unsigned dst, const void* src, int sz) {
    asm volatile("cp.async.ca.shared.global [%0], [%1], 16, %2;\n"
                 :: "r"(dst), "l"(src), "r"(sz));
}
#define CP_COMMIT() asm volatile("cp.async.commit_group;\n" ::: "memory")
#define CP_WAIT(n)  asm volatile("cp.async.wait_group %0;\n" :: "n"(n) : "memory")

// ---------------- tf32 GEMM BMx128x16, cp.async 4-stage pipeline ----------------
#define NST 4
#define ALD 20
#define BLD 136
#define B_ST (16 * BLD)
#define GEMM_SMEM_BM(BM) ((NST * ((BM) * ALD) + NST * B_ST) * 4)

template<int BM>
__global__ void __launch_bounds__(256, 2)
tgemm_ca(const float* __restrict__ A, const float* __restrict__ B,
         float* __restrict__ C,
         int M, int N, int K, int lda, int ldb, int ldc,
         long sA, long sB, long sC)
{
    constexpr int AST = BM * ALD;
    constexpr int NI  = (BM == 128) ? 8 : 4;
    extern __shared__ float smem[];
    float* Asm = smem;                 // [NST][BM][ALD]
    float* Bsm = smem + NST * AST;     // [NST][16][BLD]

    const float* Ab = A + (long)blockIdx.z * sA;
    const float* Bb = B + (long)blockIdx.z * sB;
    float*       Cb = C + (long)blockIdx.z * sC;

    const int bm0 = blockIdx.y * BM;
    const int bn0 = blockIdx.x * 128;
    const int tid = threadIdx.x;
    const int w    = tid >> 5;
    const int lane = tid & 31;
    const int lq   = lane >> 2;
    const int lr   = lane & 3;
    const int wm0  = (BM == 128) ? (w & 3) * 32 : (w & 1) * 32;
    const int wn0  = (BM == 128) ? (w >> 2) * 64 : (w >> 1) * 32;

    const int a_row = (BM == 128) ? (tid >> 1) : (tid >> 2);
    const int a_k0  = (BM == 128) ? (tid & 1) * 8 : (tid & 3) * 4;
    const int b_r0  = tid >> 5;
    const int b_c0  = (tid & 31) * 4;
    const int b_sz  = (bn0 + b_c0 < N) ? 16 : 0;

    const unsigned a_dst0 = (unsigned)__cvta_generic_to_shared(Asm) + (a_row * ALD + a_k0) * 4;
    const unsigned b_dst0 = (unsigned)__cvta_generic_to_shared(Bsm) + (b_r0 * BLD + b_c0) * 4;

    float acc[2][NI][4];
#pragma unroll
    for (int mi = 0; mi < 2; mi++)
#pragma unroll
        for (int ni = 0; ni < NI; ni++)
#pragma unroll
            for (int r = 0; r < 4; r++) acc[mi][ni][r] = 0.f;

    const int nc = K / 16;

#pragma unroll
    for (int s = 0; s < NST - 1; s++) {
        if (s < nc) {
            const int k0 = s * 16;
            const float* ap = Ab + (long)(bm0 + a_row) * lda + k0 + a_k0;
            cp16(a_dst0 + s * AST * 4, ap, 16);
            if (BM == 128) cp16(a_dst0 + s * AST * 4 + 16, ap + 4, 16);
            const float* bp = Bb + (long)(k0 + b_r0) * ldb + bn0 + b_c0;
            cp16(b_dst0 + s * B_ST * 4,               bp,           b_sz);
            cp16(b_dst0 + s * B_ST * 4 + 8 * BLD * 4, bp + 8 * ldb, b_sz);
        }
        CP_COMMIT();
    }

    int buf = 0;
    for (int c = 0; c < nc; c++) {
        CP_WAIT(NST - 2);
        __syncthreads();

        const float* Ab_s = Asm + buf * AST;
        const float* Bb_s = Bsm + buf * B_ST;
#pragma unroll
        for (int ks = 0; ks < 2; ks++) {
            const int kb = ks * 8;
            unsigned afr[2][4];
#pragma unroll
            for (int mi = 0; mi < 2; mi++) {
                const float* r0 = Ab_s + (wm0 + 16 * mi + lq) * ALD + kb + lr;
                afr[mi][0] = tf32c(r0[0]);
                afr[mi][1] = tf32c(r0[8 * ALD]);
                afr[mi][2] = tf32c(r0[4]);
                afr[mi][3] = tf32c(r0[8 * ALD + 4]);
            }
            const float* brow0 = Bb_s + (kb + lr) * BLD + wn0 + lq;
            const float* brow1 = brow0 + 4 * BLD;
#pragma unroll
            for (int ni = 0; ni < NI; ni++) {
                unsigned b0 = tf32c(brow0[ni * 8]);
                unsigned b1 = tf32c(brow1[ni * 8]);
                mma8(acc[0][ni], afr[0], b0, b1);
                mma8(acc[1][ni], afr[1], b0, b1);
            }
        }

        const int cs = c + NST - 1;
        if (cs < nc) {
            const int st = cs % NST;
            const int k0 = cs * 16;
            const float* ap = Ab + (long)(bm0 + a_row) * lda + k0 + a_k0;
            cp16(a_dst0 + st * AST * 4, ap, 16);
            if (BM == 128) cp16(a_dst0 + st * AST * 4 + 16, ap + 4, 16);
            const float* bp = Bb + (long)(k0 + b_r0) * ldb + bn0 + b_c0;
            cp16(b_dst0 + st * B_ST * 4,               bp,           b_sz);
            cp16(b_dst0 + st * B_ST * 4 + 8 * BLD * 4, bp + 8 * ldb, b_sz);
        }
        CP_COMMIT();
        buf = (buf + 1 < NST) ? buf + 1 : 0;
    }

#pragma unroll
    for (int mi = 0; mi < 2; mi++) {
        const int row0 = bm0 + wm0 + mi * 16 + lq;
#pragma unroll
        for (int ni = 0; ni < NI; ni++) {
            const int col = bn0 + wn0 + ni * 8 + 2 * lr;
            if (col < N) {
                *(float2*)(Cb + (long)row0 * ldc + col)       = make_float2(acc[mi][ni][0], acc[mi][ni][1]);
                *(float2*)(Cb + (long)(row0 + 8) * ldc + col) = make_float2(acc[mi][ni][2], acc[mi][ni][3]);
            }
        }
    }
}

// ---------------- RMSNorm over 768 ----------------
__global__ void rms768_kernel(const float* __restrict__ in, const float* __restrict__ g,
                              float* __restrict__ out)
{
    int t = blockIdx.x;
    const float* x = in + (long)t * QLORA_;
    int tid = threadIdx.x;
    __shared__ float red[256];
    float s = 0.f;
    for (int i = tid; i < QLORA_; i += 256) { float v = x[i]; s += v * v; }
    red[tid] = s;
    __syncthreads();
    for (int st = 128; st > 0; st >>= 1) { if (tid < st) red[tid] += red[tid + st]; __syncthreads(); }
    __shared__ float rinv;
    if (tid == 0) rinv = rsqrtf(red[0] / (float)QLORA_ + EPS_);
    __syncthreads();
    for (int i = tid; i < QLORA_; i += 256)
        out[(long)t * QLORA_ + i] = x[i] * rinv * g[i];
}

// ---------------- latent -> k_in ----------------
__global__ void latent_kernel(const float* __restrict__ lat, const float* __restrict__ g,
                              const int* __restrict__ pos, float* __restrict__ kin)
{
    int t = blockIdx.x;
    const float* x = lat + (long)t * DQK;
    int tid = threadIdx.x;
    __shared__ float red[256];
    float v = x[tid];
    red[tid] = v * v;
    __syncthreads();
    for (int st = 128; st > 0; st >>= 1) { if (tid < st) red[tid] += red[tid + st]; __syncthreads(); }
    __shared__ float rinv;
    if (tid == 0) rinv = rsqrtf(red[0] / (float)KVLORA_ + EPS_);
    __syncthreads();
    kin[(long)t * DQK + tid] = v * rinv * g[tid];
    if (tid < 16) {
        float p = (float)pos[t];
        float f = p * powf(10000.f, -(float)tid / 16.f);
        float c = cosf(f), s = sinf(f);
        float x1 = x[KVLORA_ + tid];
        float x2 = x[KVLORA_ + 16 + tid];
        kin[(long)t * DQK + KVLORA_ + tid]      = x1 * c - x2 * s;
        kin[(long)t * DQK + KVLORA_ + 16 + tid] = x2 * c + x1 * s;
    }
}

// ---------------- RoPE q_pe ----------------
__global__ void rope_q_kernel(const float* __restrict__ q, const int* __restrict__ pos,
                              float* __restrict__ qin)
{
    int idx = blockIdx.x * blockDim.x + threadIdx.x;
    if (idx >= T_ * H_ * 16) return;
    int j = idx & 15;
    int h = (idx >> 4) % H_;
    int t = idx / (16 * H_);
    float p = (float)pos[t];
    float f = p * powf(10000.f, -(float)j / 16.f);
    float c = cosf(f), s = sinf(f);
    const float* qp = q + (long)t * (H_ * QHD) + h * QHD + NOPE_;
    float x1 = qp[j], x2 = qp[16 + j];
    float* o = qin + (long)t * (H_ * DQK) + h * DQK + KVLORA_;
    o[j]      = x1 * c - x2 * s;
    o[16 + j] = x2 * c + x1 * s;
}

// ---------------- flash attention v4 ----------------
// Q in A-fragment-order smem; single raw kin tile per block (K and V share it).
#define KRLD 292
#define PLD4 68
#define QF_FLOATS (4 * 36 * 32 * 4)   // 18432
#define ATTN4_SMEM ((QF_FLOATS + 64 * KRLD + 64 * PLD4 + 256 + 256 + 64 + 64) * 4)

__global__ void __launch_bounds__(256, 1)
attn4_kernel(const float* __restrict__ qin, const float* __restrict__ kin,
             float* __restrict__ olat)
{
    extern __shared__ float sm[];
    float* Qf     = sm;                      // [4 mg][36 d8][32 lane][4 reg], tf32
    float* Kraw   = Qf + QF_FLOATS;          // [64][KRLD] raw fp32 kin tile
    float* Ps     = Kraw + 64 * KRLD;        // [64][PLD4] tf32
    float* redmax = Ps + 64 * PLD4;          // [64][4]
    float* redsum = redmax + 256;
    float* m_s    = redsum + 256;
    float* l_s    = m_s + 64;

    const int h   = blockIdx.y;
    const int qb  = gridDim.x - 1 - blockIdx.x;   // heavy first
    const int i0  = qb * 64;
    const int tid = threadIdx.x;
    const int w    = tid >> 5;
    const int lane = tid & 31;
    const int wm   = (w & 1) * 32;
    const int wni  = w >> 1;
    const int wn   = wni * 16;
    const int wv   = wni * 64;
    const int lq   = lane >> 2;
    const int lr   = lane & 3;
    const float scale = 0.102062072615966f;  // 1/sqrt(96)

    // ---- Q -> fragment-order smem (pre-scaled tf32) ----
    {
        const int row   = tid >> 2;
        const int dbase = (tid & 3) * 72;
        const int mg  = row >> 4;
        const int lq8 = row & 7;
        const int rb0 = (row >> 3) & 1;
        const float* src = qin + (size_t)(i0 + row) * (H_ * DQK) + h * DQK + dbase;
#pragma unroll
        for (int i = 0; i < 18; i++) {
            float4 v = *(const float4*)(src + i * 4);
            const int d0  = dbase + i * 4;
            const int d8  = d0 >> 3;
            const int reg = rb0 + ((d0 >> 2) & 1) * 2;
            float* dst = Qf + ((mg * 36 + d8) * 32 + lq8 * 4) * 4 + reg;
            dst[0]  = __uint_as_float(tf32c(v.x * scale));
            dst[4]  = __uint_as_float(tf32c(v.y * scale));
            dst[8]  = __uint_as_float(tf32c(v.z * scale));
            dst[12] = __uint_as_float(tf32c(v.w * scale));
        }
    }
    if (tid < 64) { m_s[tid] = -1e30f; l_s[tid] = 0.f; }

    float o[2][8][4];
#pragma unroll
    for (int mi = 0; mi < 2; mi++)
#pragma unroll
        for (int ni = 0; ni < 8; ni++)
#pragma unroll
            for (int r = 0; r < 4; r++) o[mi][ni][r] = 0.f;

    const unsigned kraw_s = (unsigned)__cvta_generic_to_shared(Kraw);
    const int krow = tid >> 3;          // 0..31 (two rows per thread)
    const int kc   = (tid & 7) * 36;
    const int qmg0 = 2 * (w & 1);
    const int nkb  = qb + 1;

    for (int kb = 0; kb < nkb; kb++) {
        const int j0 = kb * 64;
        __syncthreads();    // Kraw / Ps free (also orders Qf build before first use)

        // ---- load raw kin tile (64 x 288) via cp.async ----
#pragma unroll
        for (int r2 = 0; r2 < 2; r2++) {
            const int row = krow + 32 * r2;
            const float* src = kin + (size_t)(j0 + row) * DQK + kc;
            const unsigned dst = kraw_s + (unsigned)(row * KRLD + kc) * 4;
#pragma unroll
            for (int i = 0; i < 9; i++)
                cp16(dst + i * 16, src + i * 4, 16);
        }
        CP_COMMIT();
        CP_WAIT(0);
        __syncthreads();

        // L2 prefetch next tile while computing
        if (kb + 1 < nkb) {
#pragma unroll
            for (int r2 = 0; r2 < 2; r2++) {
                const float* p = kin + (size_t)(j0 + 64 + krow + 32 * r2) * DQK + kc;
                asm volatile("prefetch.global.L2 [%0];" :: "l"(p));
                asm volatile("prefetch.global.L2 [%0];" :: "l"(p + 32));
            }
        }

        // ---- S = Q K^T ----
        float s[2][2][4];
#pragma unroll
        for (int mi = 0; mi < 2; mi++)
#pragma unroll
            for (int ni = 0; ni < 2; ni++)
#pragma unroll
                for (int r = 0; r < 4; r++) s[mi][ni][r] = 0.f;

#pragma unroll 4
        for (int d8 = 0; d8 < 36; d8++) {
            unsigned a[2][4];
#pragma unroll
            for (int mi = 0; mi < 2; mi++) {
                float4 qv = *(const float4*)(Qf + (((qmg0 + mi) * 36 + d8) * 32 + lane) * 4);
                a[mi][0] = __float_as_uint(qv.x); a[mi][1] = __float_as_uint(qv.y);
                a[mi][2] = __float_as_uint(qv.z); a[mi][3] = __float_as_uint(qv.w);
            }
#pragma unroll
            for (int ni = 0; ni < 2; ni++) {
                const float* kp = Kraw + (wn + 8 * ni + lq) * KRLD + d8 * 8 + lr;
                unsigned b0 = tf32c(kp[0]);
                unsigned b1 = tf32c(kp[4]);
                mma8(s[0][ni], a[0], b0, b1);
                mma8(s[1][ni], a[1], b0, b1);
            }
        }

        // ---- causal mask on diagonal block ----
        if (kb == qb) {
#pragma unroll
            for (int mi = 0; mi < 2; mi++)
#pragma unroll
                for (int ni = 0; ni < 2; ni++)
#pragma unroll
                    for (int r = 0; r < 4; r++) {
                        int row = wm + 16 * mi + 8 * (r >> 1) + lq;
                        int col = wn + 8 * ni + 2 * lr + (r & 1);
                        if (col > row) s[mi][ni][r] = -1e30f;
                    }
        }

        // ---- online softmax ----
#pragma unroll
        for (int mi = 0; mi < 2; mi++)
#pragma unroll
            for (int half = 0; half < 2; half++) {
                float mx = fmaxf(fmaxf(s[mi][0][2*half], s[mi][0][2*half+1]),
                                 fmaxf(s[mi][1][2*half], s[mi][1][2*half+1]));
                mx = fmaxf(mx, __shfl_xor_sync(0xffffffffu, mx, 1));
                mx = fmaxf(mx, __shfl_xor_sync(0xffffffffu, mx, 2));
                if (lr == 0) redmax[(wm + 16 * mi + 8 * half + lq) * 4 + wni] = mx;
            }
        __syncthreads();

        float alpha[2][2], mnew[2][2];
#pragma unroll
        for (int mi = 0; mi < 2; mi++)
#pragma unroll
            for (int half = 0; half < 2; half++) {
                const int row = wm + 16 * mi + 8 * half + lq;
                const float* rp = redmax + row * 4;
                float bm = fmaxf(fmaxf(rp[0], rp[1]), fmaxf(rp[2], rp[3]));
                float mo = m_s[row];
                float mn = fmaxf(mo, bm);
                mnew[mi][half]  = mn;
                alpha[mi][half] = __expf(mo - mn);
                float p0[2], p1[2];
#pragma unroll
                for (int ni = 0; ni < 2; ni++) {
                    p0[ni] = __expf(s[mi][ni][2*half]     - mn);
                    p1[ni] = __expf(s[mi][ni][2*half + 1] - mn);
                }
                float su = p0[0] + p1[0] + p0[1] + p1[1];
                su += __shfl_xor_sync(0xffffffffu, su, 1);
                su += __shfl_xor_sync(0xffffffffu, su, 2);
                if (lr == 0) redsum[row * 4 + wni] = su;
#pragma unroll
                for (int ni = 0; ni < 2; ni++) {
                    unsigned* pp = (unsigned*)(Ps + row * PLD4 + wn + 8 * ni + 2 * lr);
                    pp[0] = tf32c(p0[ni]);
                    pp[1] = tf32c(p1[ni]);
                }
            }
#pragma unroll
        for (int mi = 0; mi < 2; mi++)
#pragma unroll
            for (int ni = 0; ni < 8; ni++) {
                o[mi][ni][0] *= alpha[mi][0];
                o[mi][ni][1] *= alpha[mi][0];
                o[mi][ni][2] *= alpha[mi][1];
                o[mi][ni][3] *= alpha[mi][1];
            }
        __syncthreads();

        if (w < 2 && lr == 0) {
#pragma unroll
            for (int mi = 0; mi < 2; mi++)
#pragma unroll
                for (int half = 0; half < 2; half++) {
                    const int row = wm + 16 * mi + 8 * half + lq;
                    const float* rp = redsum + row * 4;
                    l_s[row] = l_s[row] * alpha[mi][half] + (rp[0] + rp[1] + rp[2] + rp[3]);
                    m_s[row] = mnew[mi][half];
                }
        }

        // ---- O += P @ V  (V = Kraw cols 0..255) ----
#pragma unroll
        for (int kst = 0; kst < 8; kst++) {
            unsigned a[2][4];
#pragma unroll
            for (int mi = 0; mi < 2; mi++) {
                const unsigned* p0 = (const unsigned*)(Ps + (wm + 16 * mi + lq) * PLD4) + kst * 8 + lr;
                const unsigned* p1 = p0 + 8 * PLD4;
                a[mi][0] = p0[0]; a[mi][1] = p1[0]; a[mi][2] = p0[4]; a[mi][3] = p1[4];
            }
            const float* vr0 = Kraw + (kst * 8 + lr) * KRLD + wv + lq;
            const float* vr1 = vr0 + 4 * KRLD;
#pragma unroll
            for (int ni = 0; ni < 8; ni++) {
                unsigned b0 = tf32c(vr0[ni * 8]);
                unsigned b1 = tf32c(vr1[ni * 8]);
                mma8(o[0][ni], a[0], b0, b1);
                mma8(o[1][ni], a[1], b0, b1);
            }
        }
    }

    __syncthreads();
#pragma unroll
    for (int mi = 0; mi < 2; mi++)
#pragma unroll
        for (int half = 0; half < 2; half++) {
            const int row = wm + 16 * mi + 8 * half + lq;
            const float linv = 1.f / l_s[row];
            float* dst = olat + (size_t)(i0 + row) * (H_ * KVLORA_) + h * KVLORA_;
#pragma unroll
            for (int ni = 0; ni < 8; ni++) {
                float2 v = make_float2(o[mi][ni][2*half] * linv, o[mi][ni][2*half + 1] * linv);
                *(float2*)(dst + wv + 8 * ni + 2 * lr) = v;
            }
        }
}

// ---------------- host ----------------
extern "C" void kernel_launch(void* const* d_in, const int* in_sizes, int n_in,
                              void* d_out, int out_size)
{
    const int*   positions = (const int*)  d_in[0];
    const float* hidden    = (const float*)d_in[1];
    const float* w_qa      = (const float*)d_in[2];
    const float* g_qa      = (const float*)d_in[3];
    const float* w_qb      = (const float*)d_in[4];
    const float* w_kva     = (const float*)d_in[5];
    const float* g_kva     = (const float*)d_in[6];
    const float* w_kc      = (const float*)d_in[7];
    const float* w_vc      = (const float*)d_in[8];
    const float* w_o       = (const float*)d_in[9];
    float* out = (float*)d_out;

    float *qa, *qan, *q, *lat, *kin, *qin, *olat, *ov;
    cudaGetSymbolAddress((void**)&qa,   sc_qa);
    cudaGetSymbolAddress((void**)&qan,  sc_qan);
    cudaGetSymbolAddress((void**)&q,    sc_q);
    cudaGetSymbolAddress((void**)&lat,  sc_lat);
    cudaGetSymbolAddress((void**)&kin,  sc_kin);
    cudaGetSymbolAddress((void**)&qin,  sc_qin);
    cudaGetSymbolAddress((void**)&olat, sc_olat);
    cudaGetSymbolAddress((void**)&ov,   sc_ov);

    cudaFuncSetAttribute(attn4_kernel, cudaFuncAttributeMaxDynamicSharedMemorySize, ATTN4_SMEM);
    cudaFuncSetAttribute(tgemm_ca<128>, cudaFuncAttributeMaxDynamicSharedMemorySize, GEMM_SMEM_BM(128));
    cudaFuncSetAttribute(tgemm_ca<64>,  cudaFuncAttributeMaxDynamicSharedMemorySize, GEMM_SMEM_BM(64));

    dim3 thr(256);

    // 1) qa = hidden @ w_qa  (BM=64 -> 192 CTAs)
    tgemm_ca<64><<<dim3(QLORA_/128, T_/64, 1), thr, GEMM_SMEM_BM(64)>>>(hidden, w_qa, qa,
        T_, QLORA_, HID_, HID_, QLORA_, QLORA_, 0, 0, 0);
    // 2) rmsnorm
    rms768_kernel<<<T_, thr>>>(qa, g_qa, qan);
    // 3) q = qan @ w_qb
    tgemm_ca<128><<<dim3((H_*QHD)/128, T_/128, 1), thr, GEMM_SMEM_BM(128)>>>(qan, w_qb, q,
        T_, H_*QHD, QLORA_, QLORA_, H_*QHD, H_*QHD, 0, 0, 0);
    // 4) latent = hidden @ w_kva  (BM=64 -> 96 CTAs)
    tgemm_ca<64><<<dim3((DQK+127)/128, T_/64, 1), thr, GEMM_SMEM_BM(64)>>>(hidden, w_kva, lat,
        T_, DQK, HID_, HID_, DQK, DQK, 0, 0, 0);
    // 5) k_in build
    latent_kernel<<<T_, thr>>>(lat, g_kva, positions, kin);
    // 6) q_lat batched over heads
    tgemm_ca<128><<<dim3(KVLORA_/128, T_/128, H_), thr, GEMM_SMEM_BM(128)>>>(q, w_kc, qin,
        T_, KVLORA_, NOPE_, H_*QHD, KVLORA_, H_*DQK,
        (long)QHD, (long)NOPE_*KVLORA_, (long)DQK);
    // 7) rope q_pe
    rope_q_kernel<<<(T_*H_*16 + 255)/256, thr>>>(q, positions, qin);
    // 8) attention
    attn4_kernel<<<dim3(T_/64, H_), thr, ATTN4_SMEM>>>(qin, kin, olat);
    // 9) v-proj batched
    tgemm_ca<128><<<dim3(1, T_/128, H_), thr, GEMM_SMEM_BM(128)>>>(olat, w_vc, ov,
        T_, VDIM_, KVLORA_, H_*KVLORA_, VDIM_, H_*VDIM_,
        (long)KVLORA_, (long)KVLORA_*VDIM_, (long)VDIM_);
    // 10) out = ov @ w_o
    tgemm_ca<128><<<dim3(HID_/128, T_/128, 1), thr, GEMM_SMEM_BM(128)>>>(ov, w_o, out,
        T_, HID_, H_*VDIM_, H_*VDIM_, HID_, HID_, 0, 0, 0);
}